// round 2
// baseline (speedup 1.0000x reference)
#include <cuda_runtime.h>

// Problem dims
#define BATCH 512
#define SEQT  512
#define IDIM  64
#define HDIM  256
#define KDIM  (HDIM + IDIM)     // 320: concatenated [h | x_t]

// Tiling
#define MB_GROUPS 8             // batch groups
#define JB_GROUPS 16            // hidden-unit groups
#define MTILE 64                // batch rows per group
#define JTILE 16                // hidden units per CTA
#define WROWS (3 * JTILE)       // 48 gate rows per CTA (r,z,n per unit)
#define NTH 128                 // threads per CTA
#define HP 324                  // smem pitch (320 + 4): float4-aligned, conflict-free

// Persistent device scratch (no cudaMalloc allowed)
__device__ float    g_h[2][BATCH * HDIM];   // ping-pong hidden state
__device__ unsigned g_cnt[MB_GROUPS];       // per-group barrier counters
__device__ unsigned g_gen[MB_GROUPS];       // per-group barrier generations (monotone)

__device__ __forceinline__ float sigmoidf_fast(float v) {
    return 1.0f / (1.0f + __expf(-v));
}

__global__ void __launch_bounds__(NTH, 1) gru_fused_kernel(
    const float* __restrict__ x,      // [B, T, I]
    const float* __restrict__ w_ih,   // [3H, I]
    const float* __restrict__ w_hh,   // [3H, H]
    const float* __restrict__ b_ih,   // [3H]
    const float* __restrict__ b_hh,   // [3H]
    const float* __restrict__ w_lin,  // [1, H]
    const float* __restrict__ b_lin,  // [1]
    float* __restrict__ out)          // [2B]
{
    extern __shared__ float smem[];
    float* h_sm = smem;                    // [MTILE][HP]: cols 0..255 = h, 256..319 = x_t
    float* w_sm = smem + MTILE * HP;       // [WROWS][HP]: cols 0..255 = w_hh, 256..319 = w_ih

    const int tid = threadIdx.x;
    const int jb  = blockIdx.x;            // 0..15 hidden group
    const int mb  = blockIdx.y;            // 0..7  batch group
    const int ug  = tid & 7;               // unit-group lane (0..7)
    const int rg  = tid >> 3;              // row-group (0..15)

    // ---- Load this CTA's weight slice into SMEM once (persists for all 512 steps) ----
    // Local gate-row rr = u*3 + g maps to global weight row g*HDIM + jb*JTILE + u.
    for (int idx = tid; idx < WROWS * 80; idx += NTH) {
        int rr = idx / 80;
        int c4 = idx - rr * 80;            // float4 column index within 320
        int u  = rr / 3;
        int g  = rr - u * 3;
        int grow = g * HDIM + jb * JTILE + u;
        float4 v;
        if (c4 < 64)
            v = *(const float4*)(w_hh + (size_t)grow * HDIM + c4 * 4);
        else
            v = *(const float4*)(w_ih + (size_t)grow * IDIM + (c4 - 64) * 4);
        *(float4*)(w_sm + rr * HP + c4 * 4) = v;
    }

    // ---- Per-thread biases (r/z biases combine; n-gate biases must stay split) ----
    float bR[2], bZ[2], bIN[2], bHN[2];
#pragma unroll
    for (int j = 0; j < 2; j++) {
        int gi  = jb * JTILE + ug + 8 * j;
        bR[j]  = b_ih[gi] + b_hh[gi];
        bZ[j]  = b_ih[HDIM + gi] + b_hh[HDIM + gi];
        bIN[j] = b_ih[2 * HDIM + gi];
        bHN[j] = b_hh[2 * HDIM + gi];
    }

    // Quiescent barrier-generation base (stable: no concurrent writers at launch).
    const unsigned bar_base = *(volatile unsigned*)&g_gen[mb];
    unsigned bar_i = 0;

    __syncthreads();

    const size_t xrowstride = (size_t)SEQT * IDIM;
    const float* xblk = x + (size_t)(mb * MTILE) * xrowstride;

    for (int t = 0; t < SEQT; ++t) {
        // ---- Stage x_t tile into h_sm[:, 256:320] ----
        {
            const float* xbase = xblk + (size_t)t * IDIM;
            for (int idx = tid; idx < MTILE * 16; idx += NTH) {
                int row = idx >> 4, c4 = idx & 15;
                float4 v = __ldg((const float4*)(xbase + (size_t)row * xrowstride + c4 * 4));
                *(float4*)(h_sm + row * HP + HDIM + c4 * 4) = v;
            }
        }
        // ---- Stage h tile into h_sm[:, 0:256] (skip at t=0: h0 == 0) ----
        if (t > 0) {
            const float* hbase = g_h[t & 1] + (size_t)(mb * MTILE) * HDIM;
            for (int idx = tid; idx < MTILE * 64; idx += NTH) {
                int row = idx >> 6, c4 = idx & 63;
                float4 v = __ldcg((const float4*)(hbase + row * HDIM + c4 * 4));
                *(float4*)(h_sm + row * HP + c4 * 4) = v;
            }
        }
        __syncthreads();

        // ---- Register-tiled GEMM: 4 rows x 2 units x 3 gates per thread ----
        float accR[4][2], accZ[4][2], accHN[4][2], accXN[4][2];
#pragma unroll
        for (int i = 0; i < 4; i++)
#pragma unroll
            for (int j = 0; j < 2; j++) {
                accR[i][j] = 0.f; accZ[i][j] = 0.f; accHN[i][j] = 0.f; accXN[i][j] = 0.f;
            }

        const float* hr = h_sm + rg * HP;
        const float* w0 = w_sm + (ug * 3) * HP;        // unit ug
        const float* w1 = w_sm + ((ug + 8) * 3) * HP;  // unit ug+8

        if (t > 0) {
#pragma unroll 2
            for (int k = 0; k < HDIM; k += 4) {
                float4 hv[4];
                hv[0] = *(const float4*)(hr + k);
                hv[1] = *(const float4*)(hr + 16 * HP + k);
                hv[2] = *(const float4*)(hr + 32 * HP + k);
                hv[3] = *(const float4*)(hr + 48 * HP + k);
                float4 wv[2][3];
                wv[0][0] = *(const float4*)(w0 + k);
                wv[0][1] = *(const float4*)(w0 + HP + k);
                wv[0][2] = *(const float4*)(w0 + 2 * HP + k);
                wv[1][0] = *(const float4*)(w1 + k);
                wv[1][1] = *(const float4*)(w1 + HP + k);
                wv[1][2] = *(const float4*)(w1 + 2 * HP + k);
#pragma unroll
                for (int i = 0; i < 4; i++) {
                    const float4 h4 = hv[i];
#pragma unroll
                    for (int j = 0; j < 2; j++) {
                        accR[i][j]  = fmaf(h4.x, wv[j][0].x, accR[i][j]);
                        accR[i][j]  = fmaf(h4.y, wv[j][0].y, accR[i][j]);
                        accR[i][j]  = fmaf(h4.z, wv[j][0].z, accR[i][j]);
                        accR[i][j]  = fmaf(h4.w, wv[j][0].w, accR[i][j]);
                        accZ[i][j]  = fmaf(h4.x, wv[j][1].x, accZ[i][j]);
                        accZ[i][j]  = fmaf(h4.y, wv[j][1].y, accZ[i][j]);
                        accZ[i][j]  = fmaf(h4.z, wv[j][1].z, accZ[i][j]);
                        accZ[i][j]  = fmaf(h4.w, wv[j][1].w, accZ[i][j]);
                        accHN[i][j] = fmaf(h4.x, wv[j][2].x, accHN[i][j]);
                        accHN[i][j] = fmaf(h4.y, wv[j][2].y, accHN[i][j]);
                        accHN[i][j] = fmaf(h4.z, wv[j][2].z, accHN[i][j]);
                        accHN[i][j] = fmaf(h4.w, wv[j][2].w, accHN[i][j]);
                    }
                }
            }
        }
        // x-projection part (k in [256,320)): accumulates into accXN for the n gate.
#pragma unroll
        for (int k = HDIM; k < KDIM; k += 4) {
            float4 hv[4];
            hv[0] = *(const float4*)(hr + k);
            hv[1] = *(const float4*)(hr + 16 * HP + k);
            hv[2] = *(const float4*)(hr + 32 * HP + k);
            hv[3] = *(const float4*)(hr + 48 * HP + k);
            float4 wv[2][3];
            wv[0][0] = *(const float4*)(w0 + k);
            wv[0][1] = *(const float4*)(w0 + HP + k);
            wv[0][2] = *(const float4*)(w0 + 2 * HP + k);
            wv[1][0] = *(const float4*)(w1 + k);
            wv[1][1] = *(const float4*)(w1 + HP + k);
            wv[1][2] = *(const float4*)(w1 + 2 * HP + k);
#pragma unroll
            for (int i = 0; i < 4; i++) {
                const float4 h4 = hv[i];
#pragma unroll
                for (int j = 0; j < 2; j++) {
                    accR[i][j]  = fmaf(h4.x, wv[j][0].x, accR[i][j]);
                    accR[i][j]  = fmaf(h4.y, wv[j][0].y, accR[i][j]);
                    accR[i][j]  = fmaf(h4.z, wv[j][0].z, accR[i][j]);
                    accR[i][j]  = fmaf(h4.w, wv[j][0].w, accR[i][j]);
                    accZ[i][j]  = fmaf(h4.x, wv[j][1].x, accZ[i][j]);
                    accZ[i][j]  = fmaf(h4.y, wv[j][1].y, accZ[i][j]);
                    accZ[i][j]  = fmaf(h4.z, wv[j][1].z, accZ[i][j]);
                    accZ[i][j]  = fmaf(h4.w, wv[j][1].w, accZ[i][j]);
                    accXN[i][j] = fmaf(h4.x, wv[j][2].x, accXN[i][j]);
                    accXN[i][j] = fmaf(h4.y, wv[j][2].y, accXN[i][j]);
                    accXN[i][j] = fmaf(h4.z, wv[j][2].z, accXN[i][j]);
                    accXN[i][j] = fmaf(h4.w, wv[j][2].w, accXN[i][j]);
                }
            }
        }

        // ---- Gate epilogue + h update ----
        float* hout = g_h[(t + 1) & 1];
#pragma unroll
        for (int i = 0; i < 4; i++) {
            int row = rg + 16 * i;
#pragma unroll
            for (int j = 0; j < 2; j++) {
                int u = ug + 8 * j;
                float r = sigmoidf_fast(accR[i][j] + bR[j]);
                float z = sigmoidf_fast(accZ[i][j] + bZ[j]);
                float n = tanhf(accXN[i][j] + bIN[j] + r * (accHN[i][j] + bHN[j]));
                float hold = (t > 0) ? h_sm[row * HP + jb * JTILE + u] : 0.f;
                float hnew = (1.f - z) * n + z * hold;
                hout[(size_t)(mb * MTILE + row) * HDIM + jb * JTILE + u] = hnew;
            }
        }

        // ---- Per-batch-group barrier (16 CTAs). __threadfence() => gpu-scope
        // release + CCTL.IVALL (L1 invalidate), so next step's reads are fresh. ----
        bar_i++;
        __threadfence();
        __syncthreads();
        if (tid == 0) {
            const unsigned target = bar_base + bar_i;
            unsigned old = atomicAdd(&g_cnt[mb], 1u);
            if (old == JB_GROUPS - 1) {
                g_cnt[mb] = 0;
                __threadfence();
                *(volatile unsigned*)&g_gen[mb] = target;
            } else {
                while (*(volatile unsigned*)&g_gen[mb] < target) { }
                __threadfence();
            }
        }
        __syncthreads();
    }

    // ---- Output head: p = sigmoid(h_last0 @ w_lin^T + b_lin); out = [p, 1-p] ----
    // Final h lives in g_h[0] (512 steps). One CTA per batch group suffices.
    if (jb == 0) {
        const float* hf = g_h[0] + (size_t)mb * MTILE * HDIM;
        const float bl = __ldg(b_lin);
        for (int row = tid; row < MTILE; row += NTH) {
            const float* hrow = hf + (size_t)row * HDIM;
            float s = bl;
#pragma unroll 8
            for (int k = 0; k < HDIM; k++)
                s = fmaf(__ldcg(hrow + k), __ldg(w_lin + k), s);
            float p = sigmoidf_fast(s);
            int b = mb * MTILE + row;
            out[2 * b]     = p;
            out[2 * b + 1] = 1.f - p;
        }
    }
}

extern "C" void kernel_launch(void* const* d_in, const int* in_sizes, int n_in,
                              void* d_out, int out_size) {
    const float* x     = (const float*)d_in[0];
    const float* w_ih0 = (const float*)d_in[1];
    const float* w_hh0 = (const float*)d_in[2];
    const float* b_ih0 = (const float*)d_in[3];
    const float* b_hh0 = (const float*)d_in[4];
    // d_in[5..8] = layer-1 weights: dead code in the reference (output uses h_last0 only)
    const float* w_lin = (const float*)d_in[9];
    const float* b_lin = (const float*)d_in[10];
    float* out = (float*)d_out;

    const size_t smem = (size_t)(MTILE + WROWS) * HP * sizeof(float);  // 145,152 B
    cudaFuncSetAttribute(gru_fused_kernel,
                         cudaFuncAttributeMaxDynamicSharedMemorySize, (int)smem);

    dim3 grid(JB_GROUPS, MB_GROUPS);  // 16 x 8 = 128 CTAs, 1/SM, all co-resident
    gru_fused_kernel<<<grid, NTH, smem>>>(x, w_ih0, w_hh0, b_ih0, b_hh0,
                                          w_lin, b_lin, out);
}

// round 4
// speedup vs baseline: 1.2953x; 1.2953x over previous
#include <cuda_runtime.h>
#include <cstdint>

// ---------------- problem dims ----------------
#define SEQT  512
#define IDIM  64
#define HDIM  256
#define XSTR  ((size_t)SEQT * IDIM)

// ---------------- tiling ----------------
#define MB_GROUPS 8      // batch groups
#define JB_GROUPS 16     // unit groups
#define MT 64            // batch rows per CTA
#define UT 16            // hidden units per CTA
#define NTH 128          // 4 warps
#define PITCH 332        // smem row pitch in floats: 332 % 32 = 12 -> conflict-free

// ---------------- persistent scratch ----------------
__device__ float    g_h[2][MB_GROUPS][MT][HDIM];  // ping-pong hidden state
__device__ unsigned g_cnt[MB_GROUPS];
__device__ unsigned g_gen[MB_GROUPS];

__device__ __forceinline__ float sigf(float v) { return 1.0f / (1.0f + __expf(-v)); }

__device__ __forceinline__ uint32_t f2tf32(float v) {
    uint32_t u;
    asm("cvt.rna.tf32.f32 %0, %1;" : "=r"(u) : "f"(v));
    return u;
}

// D += A(16x8) * B(8x8)^T, tf32 -> f32
__device__ __forceinline__ void mma8(float* d, const uint32_t* a, const uint32_t* b) {
    asm volatile(
        "mma.sync.aligned.m16n8k8.row.col.f32.tf32.tf32.f32 "
        "{%0,%1,%2,%3}, {%4,%5,%6,%7}, {%8,%9}, {%0,%1,%2,%3};"
        : "+f"(d[0]), "+f"(d[1]), "+f"(d[2]), "+f"(d[3])
        : "r"(a[0]), "r"(a[1]), "r"(a[2]), "r"(a[3]), "r"(b[0]), "r"(b[1]));
}

__global__ void __launch_bounds__(NTH, 1) gru_hmma(
    const float* __restrict__ x,      // [B, T, I]
    const float* __restrict__ w_ih,   // [3H, I]
    const float* __restrict__ w_hh,   // [3H, H]
    const float* __restrict__ b_ih,   // [3H]
    const float* __restrict__ b_hh,   // [3H]
    const float* __restrict__ w_lin,  // [1, H]
    const float* __restrict__ b_lin,  // [1]
    float* __restrict__ out)          // [2B]
{
    extern __shared__ float smem[];
    float* h_sm = smem;                 // [MT][PITCH]: cols 0..255 h, 256..319 x_t
    float* w_sm = smem + MT * PITCH;    // [64][PITCH]: rows chain*16+u; chains r,z,nh,nx

    const int tid  = threadIdx.x;
    const int wid  = tid >> 5;
    const int lane = tid & 31;
    const int g    = lane >> 2;         // fragment row group 0..7
    const int t4   = lane & 3;          // fragment k lane 0..3
    const int jb   = blockIdx.x;        // unit group 0..15
    const int mb   = blockIdx.y;        // batch group 0..7
    const int oct  = wid >> 1;          // unit octet 0/1
    const int rowbase = (wid & 1) * 32; // rows rowbase..rowbase+31

    // ---- Fill weight SMEM once (tf32-rounded). chains: 0=r, 1=z, 2=n_h, 3=n_x ----
    for (int e = tid; e < 64 * PITCH; e += NTH) {
        int row = e / PITCH, k = e - row * PITCH;
        int ch = row >> 4, ul = row & 15, gu = jb * UT + ul;
        float v = 0.f;
        if (ch == 0) {
            if (k < HDIM)            v = w_hh[(size_t)gu * HDIM + k];
            else if (k < HDIM + IDIM) v = w_ih[(size_t)gu * IDIM + (k - HDIM)];
        } else if (ch == 1) {
            int gr = HDIM + gu;
            if (k < HDIM)            v = w_hh[(size_t)gr * HDIM + k];
            else if (k < HDIM + IDIM) v = w_ih[(size_t)gr * IDIM + (k - HDIM)];
        } else if (ch == 2) {
            if (k < HDIM)            v = w_hh[(size_t)(2 * HDIM + gu) * HDIM + k];
        } else {
            if (k >= HDIM && k < HDIM + IDIM)
                v = w_ih[(size_t)(2 * HDIM + gu) * IDIM + (k - HDIM)];
        }
        *(uint32_t*)(w_sm + e) = f2tf32(v);
    }

    // ---- Per-thread biases for my 2 output units ----
    const int u0 = oct * 8 + 2 * t4;          // local unit of D col pair
    float bR[2], bZ[2], bIN[2], bHN[2];
#pragma unroll
    for (int c = 0; c < 2; c++) {
        int gu = jb * UT + u0 + c;
        bR[c]  = b_ih[gu] + b_hh[gu];
        bZ[c]  = b_ih[HDIM + gu] + b_hh[HDIM + gu];
        bIN[c] = b_ih[2 * HDIM + gu];
        bHN[c] = b_hh[2 * HDIM + gu];
    }

    const unsigned bar_base = *(volatile unsigned*)&g_gen[mb];
    unsigned bar_i = 0;
    __syncthreads();

    const float* xblk = x + (size_t)(mb * MT) * XSTR;

    for (int t = 0; t < SEQT; ++t) {
        // ---- stage x_t ----
        for (int i = tid; i < MT * 16; i += NTH) {
            int row = i >> 4, c4 = i & 15;
            float4 v = __ldg((const float4*)(xblk + (size_t)row * XSTR + (size_t)t * IDIM + c4 * 4));
            *(float4*)(h_sm + row * PITCH + HDIM + c4 * 4) = v;
        }
        // ---- stage h (prev) ----
        if (t > 0) {
            const float* hb = &g_h[t & 1][mb][0][0];
            for (int i = tid; i < MT * 64; i += NTH) {
                int row = i >> 6, c4 = i & 63;
                float4 v = __ldcg((const float4*)(hb + row * HDIM + c4 * 4));
                *(float4*)(h_sm + row * PITCH + c4 * 4) = v;
            }
        }
        __syncthreads();

        // ---- HMMA: acc[rt][chain][4]; rt = row tiles {0,16}; chains r,z,nh / r,z,nx ----
        float accR[2][4], accZ[2][4], accH[2][4], accX[2][4];
#pragma unroll
        for (int rt = 0; rt < 2; rt++)
#pragma unroll
            for (int j = 0; j < 4; j++) {
                accR[rt][j] = 0.f; accZ[rt][j] = 0.f; accH[rt][j] = 0.f; accX[rt][j] = 0.f;
            }

        const float* a0p = h_sm + (rowbase + g) * PITCH + t4;       // row g,    col kb+t4
        const float* b0p = w_sm + (oct * 8 + g) * PITCH + t4;       // gaterow base (chain 0)

        if (t > 0) {
#pragma unroll 4
            for (int kb = 0; kb < HDIM; kb += 8) {
                uint32_t a[2][4], br[2], bz[2], bh[2];
#pragma unroll
                for (int rt = 0; rt < 2; rt++) {
                    const float* ap = a0p + rt * 16 * PITCH + kb;
                    a[rt][0] = *(const uint32_t*)(ap);
                    a[rt][1] = *(const uint32_t*)(ap + 8 * PITCH);
                    a[rt][2] = *(const uint32_t*)(ap + 4);
                    a[rt][3] = *(const uint32_t*)(ap + 8 * PITCH + 4);
                }
                br[0] = *(const uint32_t*)(b0p + kb);
                br[1] = *(const uint32_t*)(b0p + kb + 4);
                bz[0] = *(const uint32_t*)(b0p + 16 * PITCH + kb);
                bz[1] = *(const uint32_t*)(b0p + 16 * PITCH + kb + 4);
                bh[0] = *(const uint32_t*)(b0p + 32 * PITCH + kb);
                bh[1] = *(const uint32_t*)(b0p + 32 * PITCH + kb + 4);
#pragma unroll
                for (int rt = 0; rt < 2; rt++) {
                    mma8(accR[rt], a[rt], br);
                    mma8(accZ[rt], a[rt], bz);
                    mma8(accH[rt], a[rt], bh);
                }
            }
        }
#pragma unroll
        for (int kb = HDIM; kb < HDIM + IDIM; kb += 8) {
            uint32_t a[2][4], br[2], bz[2], bx[2];
#pragma unroll
            for (int rt = 0; rt < 2; rt++) {
                const float* ap = a0p + rt * 16 * PITCH + kb;
                a[rt][0] = *(const uint32_t*)(ap);
                a[rt][1] = *(const uint32_t*)(ap + 8 * PITCH);
                a[rt][2] = *(const uint32_t*)(ap + 4);
                a[rt][3] = *(const uint32_t*)(ap + 8 * PITCH + 4);
            }
            br[0] = *(const uint32_t*)(b0p + kb);
            br[1] = *(const uint32_t*)(b0p + kb + 4);
            bz[0] = *(const uint32_t*)(b0p + 16 * PITCH + kb);
            bz[1] = *(const uint32_t*)(b0p + 16 * PITCH + kb + 4);
            bx[0] = *(const uint32_t*)(b0p + 48 * PITCH + kb);
            bx[1] = *(const uint32_t*)(b0p + 48 * PITCH + kb + 4);
#pragma unroll
            for (int rt = 0; rt < 2; rt++) {
                mma8(accR[rt], a[rt], br);
                mma8(accZ[rt], a[rt], bz);
                mma8(accX[rt], a[rt], bx);
            }
        }

        // ---- epilogue: gates are register-local per (row, unit pair) ----
        const int po = (t + 1) & 1;
#pragma unroll
        for (int rt = 0; rt < 2; rt++) {
#pragma unroll
            for (int rr = 0; rr < 2; rr++) {
                int row = rowbase + rt * 16 + g + rr * 8;
                float hn2[2];
#pragma unroll
                for (int c = 0; c < 2; c++) {
                    int j = rr * 2 + c;
                    float r = sigf(accR[rt][j] + bR[c]);
                    float z = sigf(accZ[rt][j] + bZ[c]);
                    float n = tanhf(accX[rt][j] + bIN[c] + r * (accH[rt][j] + bHN[c]));
                    float hp = (t > 0) ? h_sm[row * PITCH + jb * UT + u0 + c] : 0.f;
                    hn2[c] = fmaf(z, hp - n, n);
                }
                *(float2*)&g_h[po][mb][row][jb * UT + u0] = make_float2(hn2[0], hn2[1]);
            }
        }

        // ---- per-batch-group barrier across 16 CTAs ----
        bar_i++;
        __threadfence();
        __syncthreads();
        if (tid == 0) {
            const unsigned target = bar_base + bar_i;
            unsigned old = atomicAdd(&g_cnt[mb], 1u);
            if (old == JB_GROUPS - 1) {
                g_cnt[mb] = 0;
                __threadfence();
                *(volatile unsigned*)&g_gen[mb] = target;
            } else {
                while (*(volatile unsigned*)&g_gen[mb] < target) { }
                __threadfence();
            }
        }
        __syncthreads();
    }

    // ---- head: p = sigmoid(h_last . w_lin + b_lin); out = [p, 1-p] interleaved ----
    if (jb == 0) {
        int row = tid >> 1, half = tid & 1;
        const float* hr = &g_h[0][mb][row][half * 128];
        const float* wl = w_lin + half * 128;
        float s = 0.f;
#pragma unroll 8
        for (int k = 0; k < 128; k++) s = fmaf(__ldcg(hr + k), __ldg(wl + k), s);
        s += __shfl_xor_sync(0xffffffffu, s, 1);
        if (half == 0) {
            float p = sigf(s + __ldg(b_lin));
            int gb = mb * MT + row;
            out[2 * gb]     = p;
            out[2 * gb + 1] = 1.f - p;
        }
    }
}

extern "C" void kernel_launch(void* const* d_in, const int* in_sizes, int n_in,
                              void* d_out, int out_size) {
    const float* x     = (const float*)d_in[0];
    const float* w_ih0 = (const float*)d_in[1];
    const float* w_hh0 = (const float*)d_in[2];
    const float* b_ih0 = (const float*)d_in[3];
    const float* b_hh0 = (const float*)d_in[4];
    // d_in[5..8]: layer-1 GRU weights — dead code (output uses layer-0 h_last only)
    const float* w_lin = (const float*)d_in[9];
    const float* b_lin = (const float*)d_in[10];
    float* out = (float*)d_out;

    const size_t smem = (size_t)(MT + 64) * PITCH * sizeof(float);  // 169,984 B
    cudaFuncSetAttribute(gru_hmma, cudaFuncAttributeMaxDynamicSharedMemorySize, (int)smem);

    dim3 grid(JB_GROUPS, MB_GROUPS);   // 16 x 8 = 128 CTAs, 1/SM, all co-resident
    gru_hmma<<<grid, NTH, smem>>>(x, w_ih0, w_hh0, b_ih0, b_hh0, w_lin, b_lin, out);
}

// round 5
// speedup vs baseline: 1.7244x; 1.3313x over previous
#include <cuda_runtime.h>
#include <cuda_bf16.h>
#include <cstdint>

// ---------------- problem dims ----------------
#define SEQT  512
#define IDIM  64
#define HDIM  256
#define XSTR  ((size_t)SEQT * IDIM)

// ---------------- tiling ----------------
#define CLUSTER 8        // CTAs per cluster: each owns 32 hidden units
#define NBG     16       // batch groups (clusters)
#define MT      32       // batch rows per cluster
#define NTH     256      // 8 warps
#define PB      336      // A/W row pitch in bf16 elems (336 % 64 == 16 -> conflict-free)
#define ROWB    (PB * 2) // 672 bytes per row
#define WROWS   128      // gate rows per CTA: 4 chains (r,z,nh,nx) x 32 units
#define WBYTES  (WROWS * ROWB)    // 86016
#define ABUF    (MT * ROWB)       // 21504 per buffer
#define SMEMSZ  (WBYTES + 2 * ABUF)  // 129024

// pair-permuted column order within each 16-col block:
// elems (2c, 2c+1, 2c+8, 2c+9) land contiguous -> one LDS.64 per mma fragment
__device__ __forceinline__ int perm(int k) {
    int j = k & 15;
    return (k & ~15) + ((j >> 1) & 3) * 4 + ((j >> 3) << 1) + (j & 1);
}

__device__ __forceinline__ float sigf(float v) { return 1.0f / (1.0f + __expf(-v)); }

__device__ __forceinline__ uint32_t smem_u32(const void* p) {
    uint32_t a;
    asm("{ .reg .u64 t; cvta.to.shared.u64 t, %1; cvt.u32.u64 %0, t; }" : "=r"(a) : "l"(p));
    return a;
}
__device__ __forceinline__ uint32_t pack_bf16x2(float lo, float hi) {
    uint32_t r;
    asm("cvt.rn.bf16x2.f32 %0, %1, %2;" : "=r"(r) : "f"(hi), "f"(lo));
    return r;
}
__device__ __forceinline__ void lds2(uint32_t& x, uint32_t& y, uint32_t addr) {
    asm volatile("ld.shared.v2.b32 {%0, %1}, [%2];" : "=r"(x), "=r"(y) : "r"(addr));
}
__device__ __forceinline__ void st_cluster(uint32_t laddr, int rank, uint32_t v) {
    asm volatile("{ .reg .b32 ra; mapa.shared::cluster.u32 ra, %0, %1; "
                 "st.shared::cluster.b32 [ra], %2; }"
                 :: "r"(laddr), "r"(rank), "r"(v) : "memory");
}
#define CLUSTER_SYNC() do { \
    asm volatile("barrier.cluster.arrive.aligned;" ::: "memory"); \
    asm volatile("barrier.cluster.wait.aligned;"   ::: "memory"); } while (0)

// D += A(16x16) * B(16x8)^T, bf16 -> f32
__device__ __forceinline__ void mma16(float* d, uint32_t a0, uint32_t a1, uint32_t a2,
                                      uint32_t a3, uint32_t b0, uint32_t b1) {
    asm volatile(
        "mma.sync.aligned.m16n8k16.row.col.f32.bf16.bf16.f32 "
        "{%0,%1,%2,%3}, {%4,%5,%6,%7}, {%8,%9}, {%0,%1,%2,%3};"
        : "+f"(d[0]), "+f"(d[1]), "+f"(d[2]), "+f"(d[3])
        : "r"(a0), "r"(a1), "r"(a2), "r"(a3), "r"(b0), "r"(b1));
}

__global__ void __launch_bounds__(NTH, 1) __cluster_dims__(CLUSTER, 1, 1)
gru_bf16(const float* __restrict__ x,      // [B, T, I]
         const float* __restrict__ w_ih,   // [3H, I]
         const float* __restrict__ w_hh,   // [3H, H]
         const float* __restrict__ b_ih,   // [3H]
         const float* __restrict__ b_hh,   // [3H]
         const float* __restrict__ w_lin,  // [1, H]
         const float* __restrict__ b_lin,  // [1]
         float* __restrict__ out)          // [2B]
{
    extern __shared__ char smem[];
    const uint32_t sbase = smem_u32(smem);
    const uint32_t w_s = sbase;            // weights [128][PB] bf16
    const uint32_t a_s = sbase + WBYTES;   // A double buffer [2][MT][PB] bf16

    const int tid  = threadIdx.x;
    const int wid  = tid >> 5;
    const int lane = tid & 31;
    const int g    = lane >> 2;        // fragment row 0..7
    const int c    = lane & 3;         // fragment k-lane 0..3
    const int mt   = wid & 1;          // m-tile: rows mt*16 .. +16
    const int oct  = wid >> 1;         // unit octet 0..3
    const int rank = blockIdx.x;       // cluster rank 0..7 (units rank*32 .. +32)
    const int bg   = blockIdx.y;       // batch group 0..15

    // ---- zero A buffers (h(0)=0; pads never read but kept clean) ----
    for (int e = tid; e < 2 * MT * PB / 2; e += NTH)
        *(uint32_t*)(smem + WBYTES + e * 4) = 0u;

    // ---- weights -> SMEM bf16, permuted. rows: chain*32+u; chains r,z,nh,nx ----
    for (int e = tid; e < WROWS * PB; e += NTH) {
        int row = e / PB, k = e - row * PB;
        int ch = row >> 5, u = row & 31, gu = rank * 32 + u;
        float v = 0.f;
        if (k < 320) {
            if (ch == 0) {
                v = (k < HDIM) ? w_hh[(size_t)gu * HDIM + k]
                               : w_ih[(size_t)gu * IDIM + (k - HDIM)];
            } else if (ch == 1) {
                int gr = HDIM + gu;
                v = (k < HDIM) ? w_hh[(size_t)gr * HDIM + k]
                               : w_ih[(size_t)gr * IDIM + (k - HDIM)];
            } else if (ch == 2) {
                if (k < HDIM) v = w_hh[(size_t)(2 * HDIM + gu) * HDIM + k];
            } else {
                if (k >= HDIM) v = w_ih[(size_t)(2 * HDIM + gu) * IDIM + (k - HDIM)];
            }
        }
        *(__nv_bfloat16*)(smem + row * ROWB + (k < 320 ? perm(k) : k) * 2) =
            __float2bfloat16(v);
    }

    // ---- per-thread biases for my 2 units ----
    const int u0 = oct * 8 + 2 * c;
    float bR[2], bZ[2], bIN[2], bHN[2];
#pragma unroll
    for (int j = 0; j < 2; j++) {
        int gu = rank * 32 + u0 + j;
        bR[j]  = b_ih[gu] + b_hh[gu];
        bZ[j]  = b_ih[HDIM + gu] + b_hh[HDIM + gu];
        bIN[j] = b_ih[2 * HDIM + gu];
        bHN[j] = b_hh[2 * HDIM + gu];
    }

    // ---- stage x(0) into buffer 0 ----
    {
        const float* xb = x + (size_t)(bg * MT) * XSTR;
#pragma unroll
        for (int q = 0; q < 2; q++) {
            int fi = tid + q * NTH;                 // 512 float4 total
            int row = fi >> 4, c4 = fi & 15, k0 = 256 + c4 * 4;
            float4 v = __ldg((const float4*)(xb + (size_t)row * XSTR + c4 * 4));
            *(uint32_t*)(smem + WBYTES + row * ROWB + perm(k0) * 2)     = pack_bf16x2(v.x, v.y);
            *(uint32_t*)(smem + WBYTES + row * ROWB + perm(k0 + 2) * 2) = pack_bf16x2(v.z, v.w);
        }
    }
    __syncthreads();
    CLUSTER_SYNC();

    // ---- per-warp fragment base addresses (k-offset added as constants) ----
    const uint32_t aoff = (uint32_t)(mt * 16 + g) * ROWB + 8u * c;   // + par*ABUF + kb*32
    const uint32_t bR_a = w_s + (uint32_t)(0 * 32 + oct * 8 + g) * ROWB + 8u * c;
    const uint32_t bZ_a = bR_a + 32u * ROWB;
    const uint32_t bH_a = bR_a + 64u * ROWB;
    const uint32_t bX_a = bR_a + 96u * ROWB;

    float hprev[4] = {0.f, 0.f, 0.f, 0.f};
    const uint32_t kcol_pos = (uint32_t)perm(rank * 32 + u0) * 2;    // my h pair position

#pragma unroll 1
    for (int t = 0; t < SEQT; ++t) {
        const uint32_t acur = a_s + (uint32_t)(t & 1) * ABUF;
        const uint32_t anxt = a_s + (uint32_t)((t + 1) & 1) * ABUF;

        // ---- stage x(t+1) into next buffer (overlaps with MMA) ----
        if (t + 1 < SEQT) {
            const float* xb = x + (size_t)(bg * MT) * XSTR + (size_t)(t + 1) * IDIM;
            const uint32_t nb = anxt - sbase;
#pragma unroll
            for (int q = 0; q < 2; q++) {
                int fi = tid + q * NTH;
                int row = fi >> 4, c4 = fi & 15, k0 = 256 + c4 * 4;
                float4 v = __ldg((const float4*)(xb + (size_t)row * XSTR + c4 * 4));
                *(uint32_t*)(smem + nb + row * ROWB + perm(k0) * 2)     = pack_bf16x2(v.x, v.y);
                *(uint32_t*)(smem + nb + row * ROWB + perm(k0 + 2) * 2) = pack_bf16x2(v.z, v.w);
            }
        }

        // ---- HMMA: 20 k-blocks of 16; h-part feeds r,z,nh; x-part feeds r,z,nx ----
        float dR[4] = {0, 0, 0, 0}, dZ[4] = {0, 0, 0, 0};
        float dH[4] = {0, 0, 0, 0}, dX[4] = {0, 0, 0, 0};
        const uint32_t ap0 = acur + aoff;            // row mt*16+g
        const uint32_t ap1 = ap0 + 8u * ROWB;        // row mt*16+g+8
#pragma unroll
        for (int kb = 0; kb < 16; kb++) {            // k in [0,256): h columns
            const uint32_t o = (uint32_t)kb * 32u;
            uint32_t a0, a2, a1, a3, r0, r1, z0, z1, h0, h1;
            lds2(a0, a2, ap0 + o);
            lds2(a1, a3, ap1 + o);
            lds2(r0, r1, bR_a + o);
            lds2(z0, z1, bZ_a + o);
            lds2(h0, h1, bH_a + o);
            mma16(dR, a0, a1, a2, a3, r0, r1);
            mma16(dZ, a0, a1, a2, a3, z0, z1);
            mma16(dH, a0, a1, a2, a3, h0, h1);
        }
#pragma unroll
        for (int kb = 16; kb < 20; kb++) {           // k in [256,320): x columns
            const uint32_t o = (uint32_t)kb * 32u;
            uint32_t a0, a2, a1, a3, r0, r1, z0, z1, x0, x1;
            lds2(a0, a2, ap0 + o);
            lds2(a1, a3, ap1 + o);
            lds2(r0, r1, bR_a + o);
            lds2(z0, z1, bZ_a + o);
            lds2(x0, x1, bX_a + o);
            mma16(dR, a0, a1, a2, a3, r0, r1);
            mma16(dZ, a0, a1, a2, a3, z0, z1);
            mma16(dX, a0, a1, a2, a3, x0, x1);
        }

        // ---- gate epilogue (register-local; exact fp32 hprev for z*h) ----
        float hn[4];
#pragma unroll
        for (int i = 0; i < 4; i++) {
            int j = i & 1;
            float r = sigf(dR[i] + bR[j]);
            float z = sigf(dZ[i] + bZ[j]);
            float n = tanhf(dX[i] + bIN[j] + r * (dH[i] + bHN[j]));
            hn[i] = fmaf(z, hprev[i] - n, n);
            hprev[i] = hn[i];
        }

        // ---- DSMEM exchange: my (row, unit-pair) h values to all 8 peers ----
        const uint32_t w0 = pack_bf16x2(hn[0], hn[1]);   // row mt*16+g
        const uint32_t w1 = pack_bf16x2(hn[2], hn[3]);   // row mt*16+g+8
        const uint32_t d0 = anxt + (uint32_t)(mt * 16 + g) * ROWB + kcol_pos;
        const uint32_t d1 = d0 + 8u * ROWB;
#pragma unroll
        for (int p = 0; p < CLUSTER; p++) {
            st_cluster(d0, p, w0);
            st_cluster(d1, p, w1);
        }
        CLUSTER_SYNC();   // release my stores / acquire peers'; also orders x-stage
    }

    // ---- head (rank 0): p = sigmoid(h_last . w_lin + b_lin); out = [p, 1-p] ----
    // h_last lives bf16 in buffer 0 (t=511 wrote buffer (512)&1 = 0)
    if (rank == 0) {
        const int row = tid >> 3, seg = tid & 7;
        const uint32_t hb = a_s - sbase + (uint32_t)row * ROWB;
        float s = 0.f;
#pragma unroll
        for (int kk = 0; kk < 32; kk += 2) {
            int k = seg * 32 + kk;
            uint32_t v = *(const uint32_t*)(smem + hb + perm(k) * 2);
            float lo = __uint_as_float(v << 16);
            float hi = __uint_as_float(v & 0xffff0000u);
            s = fmaf(lo, __ldg(w_lin + k), s);
            s = fmaf(hi, __ldg(w_lin + k + 1), s);
        }
        s += __shfl_xor_sync(0xffffffffu, s, 1);
        s += __shfl_xor_sync(0xffffffffu, s, 2);
        s += __shfl_xor_sync(0xffffffffu, s, 4);
        if (seg == 0) {
            float p = sigf(s + __ldg(b_lin));
            int gb = bg * MT + row;
            out[2 * gb]     = p;
            out[2 * gb + 1] = 1.f - p;
        }
    }
}

extern "C" void kernel_launch(void* const* d_in, const int* in_sizes, int n_in,
                              void* d_out, int out_size) {
    const float* x     = (const float*)d_in[0];
    const float* w_ih0 = (const float*)d_in[1];
    const float* w_hh0 = (const float*)d_in[2];
    const float* b_ih0 = (const float*)d_in[3];
    const float* b_hh0 = (const float*)d_in[4];
    // d_in[5..8]: layer-1 GRU weights — dead code (output uses layer-0 h_last only)
    const float* w_lin = (const float*)d_in[9];
    const float* b_lin = (const float*)d_in[10];
    float* out = (float*)d_out;

    cudaFuncSetAttribute(gru_bf16, cudaFuncAttributeMaxDynamicSharedMemorySize, SMEMSZ);

    dim3 grid(CLUSTER, NBG);   // 8 x 16 = 128 CTAs = 16 clusters of 8
    gru_bf16<<<grid, NTH, SMEMSZ>>>(x, w_ih0, w_hh0, b_ih0, b_hh0, w_lin, b_lin, out);
}

// round 6
// speedup vs baseline: 2.2106x; 1.2820x over previous
#include <cuda_runtime.h>
#include <cuda_bf16.h>
#include <cstdint>

// ---------------- problem dims ----------------
#define SEQT  512
#define IDIM  64
#define HDIM  256
#define XSTR  ((size_t)SEQT * IDIM)

// ---------------- tiling ----------------
#define CLUSTER 8        // CTAs per cluster: each owns 32 hidden units
#define NBG     16       // batch groups (clusters); each covers 32 rows = 2 streams x 16
#define MTG     16       // batch rows per stream
#define NTH     256      // 8 warps: warps 0-3 = stream 0, warps 4-7 = stream 1
#define PB      336      // row pitch in bf16 elems (336 % 64 == 16 -> conflict-free)
#define ROWB    (PB * 2) // 672 bytes per row
#define WROWS   128      // gate rows per CTA: 4 chains (r,z,nh,nx) x 32 units
#define WBYTES  (WROWS * ROWB)          // 86016
#define ABUF    (MTG * ROWB)            // 10752 per buffer
#define SMEMSZ  (WBYTES + 4 * ABUF)     // 129024: [stream][parity] buffers
#define TXBYTES (CLUSTER * MTG * 32 * 2)  // 8192 bytes of h per stream phase

// pair-permuted column order within each 16-col block:
// elems (2c, 2c+1, 2c+8, 2c+9) land contiguous -> one LDS.64 per mma fragment
__device__ __forceinline__ int perm(int k) {
    int j = k & 15;
    return (k & ~15) + ((j >> 1) & 3) * 4 + ((j >> 3) << 1) + (j & 1);
}

__device__ __forceinline__ float sigf(float v) { return 1.0f / (1.0f + __expf(-v)); }
__device__ __forceinline__ float tanh_acc(float v) {
    v = fminf(fmaxf(v, -10.f), 10.f);
    float e = __expf(-2.f * v);
    return __fdividef(1.f - e, 1.f + e);
}

__device__ __forceinline__ uint32_t smem_u32(const void* p) {
    uint32_t a;
    asm("{ .reg .u64 t; cvta.to.shared.u64 t, %1; cvt.u32.u64 %0, t; }" : "=r"(a) : "l"(p));
    return a;
}
__device__ __forceinline__ uint32_t pack_bf16x2(float lo, float hi) {
    uint32_t r;
    asm("cvt.rn.bf16x2.f32 %0, %1, %2;" : "=r"(r) : "f"(hi), "f"(lo));
    return r;
}
__device__ __forceinline__ void lds2(uint32_t& x, uint32_t& y, uint32_t addr) {
    asm volatile("ld.shared.v2.b32 {%0, %1}, [%2];" : "=r"(x), "=r"(y) : "r"(addr));
}
__device__ __forceinline__ uint32_t mapa_u32(uint32_t laddr, int rank) {
    uint32_t r;
    asm("mapa.shared::cluster.u32 %0, %1, %2;" : "=r"(r) : "r"(laddr), "r"(rank));
    return r;
}
// store 4B into peer SMEM; counts 4 tx bytes on the peer's mbarrier
__device__ __forceinline__ void st_async_b32(uint32_t raddr, uint32_t val, uint32_t rmbar) {
    asm volatile("st.async.shared::cluster.mbarrier::complete_tx::bytes.b32 [%0], %1, [%2];"
                 :: "r"(raddr), "r"(val), "r"(rmbar) : "memory");
}
#define MBARRIER_INIT(mb, c) \
    asm volatile("mbarrier.init.shared.b64 [%0], %1;" \
                 :: "r"((uint32_t)(mb)), "r"((uint32_t)(c)) : "memory")
#define MBARRIER_ARRIVE(mb) \
    asm volatile("mbarrier.arrive.shared.b64 _, [%0];" :: "r"((uint32_t)(mb)) : "memory")
#define MBARRIER_ARRIVE_EXPECT_TX(mb, n) \
    asm volatile("mbarrier.arrive.expect_tx.shared.b64 _, [%0], %1;" \
                 :: "r"((uint32_t)(mb)), "r"((uint32_t)(n)) : "memory")
#define MBARRIER_WAIT_PARITY(mb, par) do { \
    uint32_t _m = (uint32_t)(mb), _p = (uint32_t)(par), _d; \
    asm volatile("{\n\t.reg .pred p;\n\t" \
        "mbarrier.try_wait.parity.acquire.cta.shared::cta.b64 p, [%1], %2;\n\t" \
        "selp.b32 %0, 1, 0, p;\n\t}" : "=r"(_d) : "r"(_m), "r"(_p) : "memory"); \
    if (!_d) { \
        asm volatile("{\n\t.reg .pred P1;\n\t" \
            "WL_%=:\n\t" \
            "mbarrier.try_wait.parity.acquire.cta.shared::cta.b64 P1, [%0], %1, 0x989680;\n\t" \
            "@P1 bra.uni WD_%=;\n\tbra.uni WL_%=;\n\tWD_%=:\n\t}" \
            :: "r"(_m), "r"(_p) : "memory"); \
    } } while (0)
#define CLUSTER_SYNC() do { \
    asm volatile("barrier.cluster.arrive.aligned;" ::: "memory"); \
    asm volatile("barrier.cluster.wait.aligned;"   ::: "memory"); } while (0)

// D += A(16x16) * B(16x8)^T, bf16 -> f32
__device__ __forceinline__ void mma16(float* d, uint32_t a0, uint32_t a1, uint32_t a2,
                                      uint32_t a3, uint32_t b0, uint32_t b1) {
    asm volatile(
        "mma.sync.aligned.m16n8k16.row.col.f32.bf16.bf16.f32 "
        "{%0,%1,%2,%3}, {%4,%5,%6,%7}, {%8,%9}, {%0,%1,%2,%3};"
        : "+f"(d[0]), "+f"(d[1]), "+f"(d[2]), "+f"(d[3])
        : "r"(a0), "r"(a1), "r"(a2), "r"(a3), "r"(b0), "r"(b1));
}

__global__ void __launch_bounds__(NTH, 1) __cluster_dims__(CLUSTER, 1, 1)
gru_wsp(const float* __restrict__ x,      // [B, T, I]
        const float* __restrict__ w_ih,   // [3H, I]
        const float* __restrict__ w_hh,   // [3H, H]
        const float* __restrict__ b_ih,   // [3H]
        const float* __restrict__ b_hh,   // [3H]
        const float* __restrict__ w_lin,  // [1, H]
        const float* __restrict__ b_lin,  // [1]
        float* __restrict__ out)          // [2B]
{
    extern __shared__ char smem[];
    __shared__ __align__(8) uint64_t mbars[4];   // [stream][parity]
    const uint32_t sbase = smem_u32(smem);

    const int tid  = threadIdx.x;
    const int wid  = tid >> 5;
    const int lane = tid & 31;
    const int gw   = wid >> 2;         // stream 0/1 (warps 0-3 / 4-7)
    const int oct  = wid & 3;          // unit octet within stream
    const int g    = lane >> 2;        // fragment row 0..7
    const int c    = lane & 3;         // fragment k-lane 0..3
    const int gtid = tid & 127;        // thread id within stream group
    const int rank = blockIdx.x;       // cluster rank: units rank*32..+32
    const int bg   = blockIdx.y;       // batch group 0..15 (rows bg*32..+32)

    // ---- zero all 4 activation buffers (h(0)=0, pads clean) ----
    for (int e = tid; e < 4 * ABUF / 4; e += NTH)
        *(uint32_t*)(smem + WBYTES + e * 4) = 0u;

    // ---- weights -> SMEM bf16, permuted. rows: chain*32+u; chains r,z,nh,nx ----
    for (int e = tid; e < WROWS * PB; e += NTH) {
        int row = e / PB, k = e - row * PB;
        int ch = row >> 5, u = row & 31, gu = rank * 32 + u;
        float v = 0.f;
        if (k < 320) {
            if (ch == 0) {
                v = (k < HDIM) ? w_hh[(size_t)gu * HDIM + k]
                               : w_ih[(size_t)gu * IDIM + (k - HDIM)];
            } else if (ch == 1) {
                int gr = HDIM + gu;
                v = (k < HDIM) ? w_hh[(size_t)gr * HDIM + k]
                               : w_ih[(size_t)gr * IDIM + (k - HDIM)];
            } else if (ch == 2) {
                if (k < HDIM) v = w_hh[(size_t)(2 * HDIM + gu) * HDIM + k];
            } else {
                if (k >= HDIM) v = w_ih[(size_t)(2 * HDIM + gu) * IDIM + (k - HDIM)];
            }
        }
        *(__nv_bfloat16*)(smem + row * ROWB + (k < 320 ? perm(k) : k) * 2) =
            __float2bfloat16(v);
    }

    // ---- per-thread biases for my 2 units ----
    const int u0 = oct * 8 + 2 * c;
    float bR[2], bZ[2], bIN[2], bHN[2];
#pragma unroll
    for (int j = 0; j < 2; j++) {
        int gu = rank * 32 + u0 + j;
        bR[j]  = b_ih[gu] + b_hh[gu];
        bZ[j]  = b_ih[HDIM + gu] + b_hh[HDIM + gu];
        bIN[j] = b_ih[2 * HDIM + gu];
        bHN[j] = b_hh[2 * HDIM + gu];
    }

    // ---- stage x(0) into buffer [gw][0] ----
    const float* xgrp = x + (size_t)(bg * 32 + gw * MTG) * XSTR;
    {
        const uint32_t b0 = WBYTES + (uint32_t)(gw * 2) * ABUF;
#pragma unroll
        for (int q = 0; q < 2; q++) {
            int fi = gtid + q * 128;
            int row = fi >> 4, c4 = fi & 15, k0 = 256 + c4 * 4;
            float4 v = __ldg((const float4*)(xgrp + (size_t)row * XSTR + c4 * 4));
            *(uint32_t*)(smem + b0 + row * ROWB + perm(k0) * 2)     = pack_bf16x2(v.x, v.y);
            *(uint32_t*)(smem + b0 + row * ROWB + perm(k0 + 2) * 2) = pack_bf16x2(v.z, v.w);
        }
    }
    if (tid == 0) {
#pragma unroll
        for (int i = 0; i < 4; i++) MBARRIER_INIT(smem_u32(&mbars[i]), 128);
    }
    __syncthreads();
    CLUSTER_SYNC();   // mbarriers + W visible cluster-wide before any st.async

    // ---- per-warp fragment addresses ----
    const uint32_t abuf_s = sbase + WBYTES;
    const uint32_t aoff = (uint32_t)g * ROWB + 8u * c;
    const uint32_t bR_a = sbase + (uint32_t)(oct * 8 + g) * ROWB + 8u * c;
    const uint32_t bZ_a = bR_a + 32u * ROWB;
    const uint32_t bH_a = bR_a + 64u * ROWB;
    const uint32_t bX_a = bR_a + 96u * ROWB;

    float hprev[4] = {0.f, 0.f, 0.f, 0.f};
    int ph[2] = {0, 0};                               // wait-parity per mbar of my stream
    const uint32_t kcol = (uint32_t)perm(rank * 32 + u0) * 2;
    const uint32_t mb_s = smem_u32(&mbars[gw * 2]);   // my stream's 2 mbars (8B apart)

#pragma unroll 1
    for (int t = 0; t < SEQT; ++t) {
        // ---- prefetch x(t+1) into registers (independent of the barrier) ----
        float4 xv0, xv1;
        if (t + 1 < SEQT) {
            int f0 = gtid, f1 = gtid + 128;
            xv0 = __ldg((const float4*)(xgrp + (size_t)(f0 >> 4) * XSTR
                                        + (size_t)(t + 1) * IDIM + (f0 & 15) * 4));
            xv1 = __ldg((const float4*)(xgrp + (size_t)(f1 >> 4) * XSTR
                                        + (size_t)(t + 1) * IDIM + (f1 & 15) * 4));
        }

        // ---- wait for h(t) (stream-local; other stream's warps keep SM busy) ----
        if (t > 0) {
            int m = t & 1;
            MBARRIER_WAIT_PARITY(mb_s + 8u * m, ph[m]);
            ph[m] ^= 1;
        }

        // ---- HMMA: 20 k-blocks; h cols feed r,z,nh; x cols feed r,z,nx ----
        const uint32_t acur = abuf_s + (uint32_t)(gw * 2 + (t & 1)) * ABUF;
        float dR[4] = {0, 0, 0, 0}, dZ[4] = {0, 0, 0, 0};
        float dH[4] = {0, 0, 0, 0}, dX[4] = {0, 0, 0, 0};
        const uint32_t ap0 = acur + aoff;
        const uint32_t ap1 = ap0 + 8u * ROWB;
#pragma unroll
        for (int kb = 0; kb < 16; kb++) {
            const uint32_t o = (uint32_t)kb * 32u;
            uint32_t a0, a2, a1, a3, r0, r1, z0, z1, h0, h1;
            lds2(a0, a2, ap0 + o);
            lds2(a1, a3, ap1 + o);
            lds2(r0, r1, bR_a + o);
            lds2(z0, z1, bZ_a + o);
            lds2(h0, h1, bH_a + o);
            mma16(dR, a0, a1, a2, a3, r0, r1);
            mma16(dZ, a0, a1, a2, a3, z0, z1);
            mma16(dH, a0, a1, a2, a3, h0, h1);
        }
#pragma unroll
        for (int kb = 16; kb < 20; kb++) {
            const uint32_t o = (uint32_t)kb * 32u;
            uint32_t a0, a2, a1, a3, r0, r1, z0, z1, x0, x1;
            lds2(a0, a2, ap0 + o);
            lds2(a1, a3, ap1 + o);
            lds2(r0, r1, bR_a + o);
            lds2(z0, z1, bZ_a + o);
            lds2(x0, x1, bX_a + o);
            mma16(dR, a0, a1, a2, a3, r0, r1);
            mma16(dZ, a0, a1, a2, a3, z0, z1);
            mma16(dX, a0, a1, a2, a3, x0, x1);
        }

        // ---- gate epilogue (register-local; exact fp32 hprev) ----
        float hn[4];
#pragma unroll
        for (int i = 0; i < 4; i++) {
            int j = i & 1;
            float r = sigf(dR[i] + bR[j]);
            float z = sigf(dZ[i] + bZ[j]);
            float n = tanh_acc(dX[i] + bIN[j] + r * (dH[i] + bHN[j]));
            hn[i] = fmaf(z, hprev[i] - n, n);
            hprev[i] = hn[i];
        }

        // ---- h exchange via st.async to all 8 CTAs (tx-counted on their mbars) ----
        const uint32_t npar = (t + 1) & 1;
        const uint32_t anxt_off = WBYTES + (uint32_t)(gw * 2 + npar) * ABUF;
        const uint32_t w0 = pack_bf16x2(hn[0], hn[1]);   // row g
        const uint32_t w1 = pack_bf16x2(hn[2], hn[3]);   // row g+8
        const uint32_t ld0 = sbase + anxt_off + (uint32_t)g * ROWB + kcol;
        const uint32_t lmb = mb_s + 8u * npar;
#pragma unroll
        for (int p = 0; p < CLUSTER; p++) {
            uint32_t rd0 = mapa_u32(ld0, p);
            uint32_t rmb = mapa_u32(lmb, p);
            st_async_b32(rd0, w0, rmb);
            st_async_b32(rd0 + 8u * ROWB, w1, rmb);
        }

        // ---- store x(t+1) into next buffer (local STS; released by arrive) ----
        if (t + 1 < SEQT) {
            int f0 = gtid, f1 = gtid + 128;
            int r0w = f0 >> 4, c40 = (f0 & 15), k00 = 256 + c40 * 4;
            int r1w = f1 >> 4, c41 = (f1 & 15), k01 = 256 + c41 * 4;
            *(uint32_t*)(smem + anxt_off + r0w * ROWB + perm(k00) * 2)     = pack_bf16x2(xv0.x, xv0.y);
            *(uint32_t*)(smem + anxt_off + r0w * ROWB + perm(k00 + 2) * 2) = pack_bf16x2(xv0.z, xv0.w);
            *(uint32_t*)(smem + anxt_off + r1w * ROWB + perm(k01) * 2)     = pack_bf16x2(xv1.x, xv1.y);
            *(uint32_t*)(smem + anxt_off + r1w * ROWB + perm(k01 + 2) * 2) = pack_bf16x2(xv1.z, xv1.w);
        }

        // ---- arrive (128 per stream); one thread also posts the 8KB tx expectation ----
        if (gtid == 0) { MBARRIER_ARRIVE_EXPECT_TX(lmb, TXBYTES); }
        else           { MBARRIER_ARRIVE(lmb); }
    }

    // ---- final wait: h(512) fully delivered into buffer [gw][0] ----
    MBARRIER_WAIT_PARITY(mb_s, ph[0]);

    // ---- head (rank 0): p = sigmoid(h_last . w_lin + b_lin); out = [p, 1-p] ----
    if (rank == 0) {
        const int row = gtid >> 3, seg = gtid & 7;
        const uint32_t hb = WBYTES + (uint32_t)(gw * 2) * ABUF + (uint32_t)row * ROWB;
        float s = 0.f;
#pragma unroll
        for (int kk = 0; kk < 32; kk += 2) {
            int k = seg * 32 + kk;
            uint32_t v = *(const uint32_t*)(smem + hb + perm(k) * 2);
            float lo = __uint_as_float(v << 16);
            float hi = __uint_as_float(v & 0xffff0000u);
            s = fmaf(lo, __ldg(w_lin + k), s);
            s = fmaf(hi, __ldg(w_lin + k + 1), s);
        }
        s += __shfl_xor_sync(0xffffffffu, s, 1);
        s += __shfl_xor_sync(0xffffffffu, s, 2);
        s += __shfl_xor_sync(0xffffffffu, s, 4);
        if (seg == 0) {
            float p = sigf(s + __ldg(b_lin));
            int gb = bg * 32 + gw * MTG + row;
            out[2 * gb]     = p;
            out[2 * gb + 1] = 1.f - p;
        }
    }

    CLUSTER_SYNC();   // no CTA exits while peers could still target its SMEM
}

extern "C" void kernel_launch(void* const* d_in, const int* in_sizes, int n_in,
                              void* d_out, int out_size) {
    const float* x     = (const float*)d_in[0];
    const float* w_ih0 = (const float*)d_in[1];
    const float* w_hh0 = (const float*)d_in[2];
    const float* b_ih0 = (const float*)d_in[3];
    const float* b_hh0 = (const float*)d_in[4];
    // d_in[5..8]: layer-1 GRU weights — dead code (output uses layer-0 h_last only)
    const float* w_lin = (const float*)d_in[9];
    const float* b_lin = (const float*)d_in[10];
    float* out = (float*)d_out;

    cudaFuncSetAttribute(gru_wsp, cudaFuncAttributeMaxDynamicSharedMemorySize, SMEMSZ);

    dim3 grid(CLUSTER, NBG);   // 8 x 16 = 128 CTAs = 16 clusters of 8
    gru_wsp<<<grid, NTH, SMEMSZ>>>(x, w_ih0, w_hh0, b_ih0, b_hh0, w_lin, b_lin, out);
}

// round 7
// speedup vs baseline: 3.2458x; 1.4683x over previous
#include <cuda_runtime.h>
#include <cuda_bf16.h>
#include <cstdint>

// ---------------- problem dims ----------------
#define SEQT  512
#define IDIM  64
#define HDIM  256
#define XSTR  ((size_t)SEQT * IDIM)

// ---------------- tiling ----------------
#define CLUSTER 8        // CTAs per cluster: each owns 32 hidden units
#define NBG     16       // batch groups (clusters); 32 rows each = 2 streams x 16
#define MTG     16       // batch rows per stream
#define NTH     256      // 8 warps: warps 0-3 = stream 0, warps 4-7 = stream 1
#define PB      336      // weight row pitch in bf16 (336 % 64 == 16 -> conflict-free)
#define ROWB    (PB * 2) // 672 bytes per weight row
#define WROWS   128      // gate rows per CTA: 4 chains (r,z,nh,nx) x 32 units
#define WBYTES  (WROWS * ROWB)          // 86016 (multiple of 512)
// A buffers: k-slab-major. 20 slabs x (16 rows x 16 cols bf16) = 20 x 512B
#define SLAB    512
#define ABUF    (20 * SLAB)             // 10240 per [stream][parity] buffer
#define SMEMSZ  (WBYTES + 4 * ABUF)     // 126976
#define TXB     (7 * 1024)              // bulk-tx bytes expected per stream phase

// within-16-col fragment order: elem e -> byte offset in a 32B row
// pairs (2c,2c+1) at byte 8c (lo), (2c+8,2c+9) at byte 8c+4 (hi)
__device__ __forceinline__ int pos16(int e) {
    return ((e >> 1) & 3) * 8 + ((e >> 3) << 2) + (e & 1) * 2;
}
// weight-side perm across full k (same order per 16-block)
__device__ __forceinline__ int perm(int k) {
    int j = k & 15;
    return (k & ~15) + ((j >> 1) & 3) * 4 + ((j >> 3) << 1) + (j & 1);
}

__device__ __forceinline__ float sigf(float v) { return 1.0f / (1.0f + __expf(-v)); }
__device__ __forceinline__ float tanh_acc(float v) {
    v = fminf(fmaxf(v, -10.f), 10.f);
    float e = __expf(-2.f * v);
    return __fdividef(1.f - e, 1.f + e);
}

__device__ __forceinline__ uint32_t smem_u32(const void* p) {
    uint32_t a;
    asm("{ .reg .u64 t; cvta.to.shared.u64 t, %1; cvt.u32.u64 %0, t; }" : "=r"(a) : "l"(p));
    return a;
}
__device__ __forceinline__ uint32_t pack_bf16x2(float lo, float hi) {
    uint32_t r;
    asm("cvt.rn.bf16x2.f32 %0, %1, %2;" : "=r"(r) : "f"(hi), "f"(lo));
    return r;
}
__device__ __forceinline__ void lds2(uint32_t& x, uint32_t& y, uint32_t addr) {
    asm volatile("ld.shared.v2.b32 {%0, %1}, [%2];" : "=r"(x), "=r"(y) : "r"(addr));
}
__device__ __forceinline__ uint32_t mapa_u32(uint32_t laddr, int rank) {
    uint32_t r;
    asm("mapa.shared::cluster.u32 %0, %1, %2;" : "=r"(r) : "r"(laddr), "r"(rank));
    return r;
}
// bulk copy local smem -> peer smem, complete_tx on peer's mbarrier
__device__ __forceinline__ void bulk_to_peer(uint32_t dst_cluster, uint32_t src_cta,
                                             uint32_t bytes, uint32_t rmbar) {
    asm volatile("cp.async.bulk.shared::cluster.shared::cta.mbarrier::complete_tx::bytes "
                 "[%0], [%1], %2, [%3];"
                 :: "r"(dst_cluster), "r"(src_cta), "r"(bytes), "r"(rmbar) : "memory");
}
#define MBARRIER_INIT(mb, c) \
    asm volatile("mbarrier.init.shared.b64 [%0], %1;" \
                 :: "r"((uint32_t)(mb)), "r"((uint32_t)(c)) : "memory")
#define MBARRIER_ARRIVE(mb) \
    asm volatile("mbarrier.arrive.shared.b64 _, [%0];" :: "r"((uint32_t)(mb)) : "memory")
#define MBARRIER_ARRIVE_EXPECT_TX(mb, n) \
    asm volatile("mbarrier.arrive.expect_tx.shared.b64 _, [%0], %1;" \
                 :: "r"((uint32_t)(mb)), "r"((uint32_t)(n)) : "memory")
#define MBARRIER_WAIT_PARITY(mb, par) do { \
    uint32_t _m = (uint32_t)(mb), _p = (uint32_t)(par), _d; \
    asm volatile("{\n\t.reg .pred p;\n\t" \
        "mbarrier.try_wait.parity.acquire.cta.shared::cta.b64 p, [%1], %2;\n\t" \
        "selp.b32 %0, 1, 0, p;\n\t}" : "=r"(_d) : "r"(_m), "r"(_p) : "memory"); \
    if (!_d) { \
        asm volatile("{\n\t.reg .pred P1;\n\t" \
            "WL_%=:\n\t" \
            "mbarrier.try_wait.parity.acquire.cta.shared::cta.b64 P1, [%0], %1, 0x989680;\n\t" \
            "@P1 bra.uni WD_%=;\n\tbra.uni WL_%=;\n\tWD_%=:\n\t}" \
            :: "r"(_m), "r"(_p) : "memory"); \
    } } while (0)
#define CLUSTER_SYNC() do { \
    asm volatile("barrier.cluster.arrive.aligned;" ::: "memory"); \
    asm volatile("barrier.cluster.wait.aligned;"   ::: "memory"); } while (0)
#define STREAM_BAR(id) \
    asm volatile("bar.sync %0, 128;" :: "r"(id) : "memory")

// D += A(16x16) * B(16x8)^T, bf16 -> f32
__device__ __forceinline__ void mma16(float* d, uint32_t a0, uint32_t a1, uint32_t a2,
                                      uint32_t a3, uint32_t b0, uint32_t b1) {
    asm volatile(
        "mma.sync.aligned.m16n8k16.row.col.f32.bf16.bf16.f32 "
        "{%0,%1,%2,%3}, {%4,%5,%6,%7}, {%8,%9}, {%0,%1,%2,%3};"
        : "+f"(d[0]), "+f"(d[1]), "+f"(d[2]), "+f"(d[3])
        : "r"(a0), "r"(a1), "r"(a2), "r"(a3), "r"(b0), "r"(b1));
}

__global__ void __launch_bounds__(NTH, 1) __cluster_dims__(CLUSTER, 1, 1)
gru_bulk(const float* __restrict__ x,      // [B, T, I]
         const float* __restrict__ w_ih,   // [3H, I]
         const float* __restrict__ w_hh,   // [3H, H]
         const float* __restrict__ b_ih,   // [3H]
         const float* __restrict__ b_hh,   // [3H]
         const float* __restrict__ w_lin,  // [1, H]
         const float* __restrict__ b_lin,  // [1]
         float* __restrict__ out)          // [2B]
{
    extern __shared__ char smem[];
    __shared__ __align__(8) uint64_t mbars[4];   // [stream][parity]
    const uint32_t sbase = smem_u32(smem);

    const int tid  = threadIdx.x;
    const int wid  = tid >> 5;
    const int lane = tid & 31;
    const int gw   = wid >> 2;         // stream 0/1
    const int oct  = wid & 3;          // unit octet within stream
    const int g    = lane >> 2;        // fragment row 0..7
    const int c    = lane & 3;         // fragment k-lane 0..3
    const int gtid = tid & 127;        // thread id within stream
    const int rank = blockIdx.x;       // cluster rank: units rank*32..+32
    const int bg   = blockIdx.y;       // batch group (rows bg*32..+32)

    // ---- zero all 4 activation buffers (h(0)=0, pads clean) ----
    for (int e = tid; e < 4 * ABUF / 4; e += NTH)
        *(uint32_t*)(smem + WBYTES + e * 4) = 0u;

    // ---- weights -> SMEM bf16, permuted. rows: chain*32+u; chains r,z,nh,nx ----
    for (int e = tid; e < WROWS * PB; e += NTH) {
        int row = e / PB, k = e - row * PB;
        int ch = row >> 5, u = row & 31, gu = rank * 32 + u;
        float v = 0.f;
        if (k < 320) {
            if (ch == 0) {
                v = (k < HDIM) ? w_hh[(size_t)gu * HDIM + k]
                               : w_ih[(size_t)gu * IDIM + (k - HDIM)];
            } else if (ch == 1) {
                int gr = HDIM + gu;
                v = (k < HDIM) ? w_hh[(size_t)gr * HDIM + k]
                               : w_ih[(size_t)gr * IDIM + (k - HDIM)];
            } else if (ch == 2) {
                if (k < HDIM) v = w_hh[(size_t)(2 * HDIM + gu) * HDIM + k];
            } else {
                if (k >= HDIM) v = w_ih[(size_t)(2 * HDIM + gu) * IDIM + (k - HDIM)];
            }
        }
        *(__nv_bfloat16*)(smem + row * ROWB + (k < 320 ? perm(k) : k) * 2) =
            __float2bfloat16(v);
    }

    // ---- per-thread biases for my 2 units ----
    const int u0 = oct * 8 + 2 * c;
    float bR[2], bZ[2], bIN[2], bHN[2];
#pragma unroll
    for (int j = 0; j < 2; j++) {
        int gu = rank * 32 + u0 + j;
        bR[j]  = b_ih[gu] + b_hh[gu];
        bZ[j]  = b_ih[HDIM + gu] + b_hh[HDIM + gu];
        bIN[j] = b_ih[2 * HDIM + gu];
        bHN[j] = b_hh[2 * HDIM + gu];
    }

    // ---- stage x(0) into buffer [gw][0], slabs 16..19 ----
    const float* xgrp = x + (size_t)(bg * 32 + gw * MTG) * XSTR;
    {
        const uint32_t b0 = WBYTES + (uint32_t)(gw * 2) * ABUF;
#pragma unroll
        for (int q = 0; q < 2; q++) {
            int fi = gtid + q * 128;
            int row = fi >> 4, c4 = fi & 15;
            int kb = 16 + (c4 >> 2), m = c4 & 3;
            float4 v = __ldg((const float4*)(xgrp + (size_t)row * XSTR + c4 * 4));
            char* slab = smem + b0 + kb * SLAB + row * 32;
            *(uint32_t*)(slab + pos16(4 * m))     = pack_bf16x2(v.x, v.y);
            *(uint32_t*)(slab + pos16(4 * m + 2)) = pack_bf16x2(v.z, v.w);
        }
    }
    if (tid == 0) {
#pragma unroll
        for (int i = 0; i < 4; i++) MBARRIER_INIT(smem_u32(&mbars[i]), 128);
    }
    __syncthreads();
    CLUSTER_SYNC();   // mbarriers + buffers visible cluster-wide before any bulk copy

    // ---- per-warp fragment addresses ----
    const uint32_t abuf_s = sbase + WBYTES;
    const uint32_t aoff = (uint32_t)g * 32 + 8u * c;           // + bi*ABUF + kb*SLAB
    const uint32_t bR_a = sbase + (uint32_t)(oct * 8 + g) * ROWB + 8u * c;
    const uint32_t bZ_a = bR_a + 32u * ROWB;
    const uint32_t bH_a = bR_a + 64u * ROWB;
    const uint32_t bX_a = bR_a + 96u * ROWB;

    float hprev[4] = {0.f, 0.f, 0.f, 0.f};
    int ph[2] = {0, 0};
    const uint32_t mb_s = smem_u32(&mbars[gw * 2]);      // my stream's 2 mbars
    const int peer = (gtid < 7) ? (gtid < rank ? gtid : gtid + 1) : 0;
    // epilogue store offsets (within my 1KB slab block)
    const uint32_t myslab_off = (uint32_t)(2 * rank) * SLAB;          // within buffer
    const uint32_t est = ((u0 >> 4) ? SLAB : 0) + (uint32_t)g * 32 + (uint32_t)pos16(u0 & 15);

#pragma unroll 1
    for (int t = 0; t < SEQT; ++t) {
        // ---- prefetch x(t+1) (independent of barrier) ----
        float4 xv0, xv1;
        if (t + 1 < SEQT) {
            int f0 = gtid, f1 = gtid + 128;
            xv0 = __ldg((const float4*)(xgrp + (size_t)(f0 >> 4) * XSTR
                                        + (size_t)(t + 1) * IDIM + (f0 & 15) * 4));
            xv1 = __ldg((const float4*)(xgrp + (size_t)(f1 >> 4) * XSTR
                                        + (size_t)(t + 1) * IDIM + (f1 & 15) * 4));
        }

        // ---- wait for h(t) ----
        if (t > 0) {
            int m = t & 1;
            MBARRIER_WAIT_PARITY(mb_s + 8u * m, ph[m]);
            ph[m] ^= 1;
        }

        // ---- HMMA over 20 k-slabs ----
        const uint32_t acur = abuf_s + (uint32_t)(gw * 2 + (t & 1)) * ABUF + aoff;
        float dR[4] = {0, 0, 0, 0}, dZ[4] = {0, 0, 0, 0};
        float dH[4] = {0, 0, 0, 0}, dX[4] = {0, 0, 0, 0};
#pragma unroll
        for (int kb = 0; kb < 16; kb++) {
            const uint32_t ao = acur + (uint32_t)kb * SLAB;
            const uint32_t wo = (uint32_t)kb * 32u;
            uint32_t a0, a2, a1, a3, r0, r1, z0, z1, h0, h1;
            lds2(a0, a2, ao);
            lds2(a1, a3, ao + 256);
            lds2(r0, r1, bR_a + wo);
            lds2(z0, z1, bZ_a + wo);
            lds2(h0, h1, bH_a + wo);
            mma16(dR, a0, a1, a2, a3, r0, r1);
            mma16(dZ, a0, a1, a2, a3, z0, z1);
            mma16(dH, a0, a1, a2, a3, h0, h1);
        }
#pragma unroll
        for (int kb = 16; kb < 20; kb++) {
            const uint32_t ao = acur + (uint32_t)kb * SLAB;
            const uint32_t wo = (uint32_t)kb * 32u;
            uint32_t a0, a2, a1, a3, r0, r1, z0, z1, x0, x1;
            lds2(a0, a2, ao);
            lds2(a1, a3, ao + 256);
            lds2(r0, r1, bR_a + wo);
            lds2(z0, z1, bZ_a + wo);
            lds2(x0, x1, bX_a + wo);
            mma16(dR, a0, a1, a2, a3, r0, r1);
            mma16(dZ, a0, a1, a2, a3, z0, z1);
            mma16(dX, a0, a1, a2, a3, x0, x1);
        }

        // ---- gate epilogue (register-local; exact fp32 hprev) ----
        float hn[4];
#pragma unroll
        for (int i = 0; i < 4; i++) {
            int j = i & 1;
            float r = sigf(dR[i] + bR[j]);
            float z = sigf(dZ[i] + bZ[j]);
            float n = tanh_acc(dX[i] + bIN[j] + r * (dH[i] + bHN[j]));
            hn[i] = fmaf(z, hprev[i] - n, n);
            hprev[i] = hn[i];
        }

        // ---- local STS: my h slab block + x(t+1), then stream barrier ----
        const uint32_t npar = (t + 1) & 1;
        const uint32_t nb_off = WBYTES + (uint32_t)(gw * 2 + npar) * ABUF;
        {
            char* dst = smem + nb_off + myslab_off + est;
            *(uint32_t*)(dst)       = pack_bf16x2(hn[0], hn[1]);   // row g
            *(uint32_t*)(dst + 256) = pack_bf16x2(hn[2], hn[3]);   // row g+8
        }
        if (t + 1 < SEQT) {
#pragma unroll
            for (int q = 0; q < 2; q++) {
                int fi = gtid + q * 128;
                int row = fi >> 4, c4 = fi & 15;
                int kb = 16 + (c4 >> 2), m = c4 & 3;
                char* slab = smem + nb_off + kb * SLAB + row * 32;
                float4 v = (q == 0) ? xv0 : xv1;
                *(uint32_t*)(slab + pos16(4 * m))     = pack_bf16x2(v.x, v.y);
                *(uint32_t*)(slab + pos16(4 * m + 2)) = pack_bf16x2(v.z, v.w);
            }
        }
        STREAM_BAR(1 + gw);   // all stream STS visible

        // ---- exchange: 7 bulk copies (1KB each) + arrivals ----
        const uint32_t lmb = mb_s + 8u * npar;
        if (gtid < 7) {
            asm volatile("fence.proxy.async.shared::cta;" ::: "memory");
            uint32_t src = sbase + nb_off + myslab_off;
            uint32_t dst = mapa_u32(src, peer);
            uint32_t rmb = mapa_u32(lmb, peer);
            bulk_to_peer(dst, src, 1024u, rmb);
        }
        if (gtid == 0) { MBARRIER_ARRIVE_EXPECT_TX(lmb, TXB); }
        else           { MBARRIER_ARRIVE(lmb); }
    }

    // ---- final wait: h(512) fully delivered into buffer [gw][0] ----
    MBARRIER_WAIT_PARITY(mb_s, ph[0]);

    // ---- head (rank 0): p = sigmoid(h_last . w_lin + b_lin); out = [p, 1-p] ----
    if (rank == 0) {
        const int row = gtid >> 3, seg = gtid & 7;
        const uint32_t hb = WBYTES + (uint32_t)(gw * 2) * ABUF;
        float s = 0.f;
#pragma unroll
        for (int kk = 0; kk < 32; kk++) {
            int k = seg * 32 + kk;
            const char* p8 = smem + hb + (k >> 4) * SLAB + row * 32 + pos16(k & 15);
            float hv = __bfloat162float(*(const __nv_bfloat16*)p8);
            s = fmaf(hv, __ldg(w_lin + k), s);
        }
        s += __shfl_xor_sync(0xffffffffu, s, 1);
        s += __shfl_xor_sync(0xffffffffu, s, 2);
        s += __shfl_xor_sync(0xffffffffu, s, 4);
        if (seg == 0) {
            float p = sigf(s + __ldg(b_lin));
            int gb = bg * 32 + gw * MTG + row;
            out[2 * gb]     = p;
            out[2 * gb + 1] = 1.f - p;
        }
    }

    CLUSTER_SYNC();   // no CTA exits while peers may still target its SMEM
}

extern "C" void kernel_launch(void* const* d_in, const int* in_sizes, int n_in,
                              void* d_out, int out_size) {
    const float* x     = (const float*)d_in[0];
    const float* w_ih0 = (const float*)d_in[1];
    const float* w_hh0 = (const float*)d_in[2];
    const float* b_ih0 = (const float*)d_in[3];
    const float* b_hh0 = (const float*)d_in[4];
    // d_in[5..8]: layer-1 GRU weights — dead code (output uses layer-0 h_last only)
    const float* w_lin = (const float*)d_in[9];
    const float* b_lin = (const float*)d_in[10];
    float* out = (float*)d_out;

    cudaFuncSetAttribute(gru_bulk, cudaFuncAttributeMaxDynamicSharedMemorySize, SMEMSZ);

    dim3 grid(CLUSTER, NBG);   // 8 x 16 = 128 CTAs = 16 clusters of 8
    gru_bulk<<<grid, NTH, SMEMSZ>>>(x, w_ih0, w_hh0, b_ih0, b_hh0, w_lin, b_lin, out);
}

// round 8
// speedup vs baseline: 3.5365x; 1.0896x over previous
#include <cuda_runtime.h>
#include <cuda_bf16.h>
#include <cstdint>

// ---------------- problem dims ----------------
#define SEQT  512
#define IDIM  64
#define HDIM  256
#define XSTR  ((size_t)SEQT * IDIM)

// ---------------- tiling ----------------
#define CLUSTER 8        // CTAs per cluster: each owns 32 hidden units
#define NBG     16       // batch groups (clusters); 32 rows each = 2 streams x 16
#define MTG     16       // batch rows per stream
#define NTH     256      // 8 warps: warps 0-3 = stream 0, warps 4-7 = stream 1
#define PB      336      // weight row pitch in bf16 (336 % 64 == 16 -> conflict-free)
#define ROWB    (PB * 2) // 672 bytes per weight row
#define WROWS   128      // gate rows per CTA: 4 chains (r,z,nh,nx) x 32 units
#define WBYTES  (WROWS * ROWB)          // 86016 (multiple of 512)
// A buffers: k-slab-major. 20 slabs x (16 rows x 16 cols bf16) = 20 x 512B
#define SLAB    512
#define ABUF    (20 * SLAB)             // 10240 per [stream][parity] buffer
#define SMEMSZ  (WBYTES + 4 * ABUF)     // 126976
#define TXB     (7 * 1024)              // bulk-tx bytes expected per stream phase

// within-16-col fragment order: elem e -> byte offset in a 32B row
__device__ __forceinline__ int pos16(int e) {
    return ((e >> 1) & 3) * 8 + ((e >> 3) << 2) + (e & 1) * 2;
}
// weight-side perm across full k (same order per 16-block)
__device__ __forceinline__ int perm(int k) {
    int j = k & 15;
    return (k & ~15) + ((j >> 1) & 3) * 4 + ((j >> 3) << 1) + (j & 1);
}

__device__ __forceinline__ float sigf(float v) { return 1.0f / (1.0f + __expf(-v)); }
__device__ __forceinline__ float tanh_acc(float v) {
    v = fminf(fmaxf(v, -10.f), 10.f);
    float e = __expf(-2.f * v);
    return __fdividef(1.f - e, 1.f + e);
}

__device__ __forceinline__ uint32_t smem_u32(const void* p) {
    uint32_t a;
    asm("{ .reg .u64 t; cvta.to.shared.u64 t, %1; cvt.u32.u64 %0, t; }" : "=r"(a) : "l"(p));
    return a;
}
__device__ __forceinline__ uint32_t pack_bf16x2(float lo, float hi) {
    uint32_t r;
    asm("cvt.rn.bf16x2.f32 %0, %1, %2;" : "=r"(r) : "f"(hi), "f"(lo));
    return r;
}
__device__ __forceinline__ void lds2(uint32_t& x, uint32_t& y, uint32_t addr) {
    asm volatile("ld.shared.v2.b32 {%0, %1}, [%2];" : "=r"(x), "=r"(y) : "r"(addr));
}
__device__ __forceinline__ uint32_t mapa_u32(uint32_t laddr, int rank) {
    uint32_t r;
    asm("mapa.shared::cluster.u32 %0, %1, %2;" : "=r"(r) : "r"(laddr), "r"(rank));
    return r;
}
__device__ __forceinline__ void bulk_to_peer(uint32_t dst_cluster, uint32_t src_cta,
                                             uint32_t bytes, uint32_t rmbar) {
    asm volatile("cp.async.bulk.shared::cluster.shared::cta.mbarrier::complete_tx::bytes "
                 "[%0], [%1], %2, [%3];"
                 :: "r"(dst_cluster), "r"(src_cta), "r"(bytes), "r"(rmbar) : "memory");
}
#define MBARRIER_INIT(mb, c) \
    asm volatile("mbarrier.init.shared.b64 [%0], %1;" \
                 :: "r"((uint32_t)(mb)), "r"((uint32_t)(c)) : "memory")
#define MBARRIER_ARRIVE(mb) \
    asm volatile("mbarrier.arrive.shared.b64 _, [%0];" :: "r"((uint32_t)(mb)) : "memory")
#define MBARRIER_ARRIVE_EXPECT_TX(mb, n) \
    asm volatile("mbarrier.arrive.expect_tx.shared.b64 _, [%0], %1;" \
                 :: "r"((uint32_t)(mb)), "r"((uint32_t)(n)) : "memory")
#define MBARRIER_WAIT_PARITY(mb, par) do { \
    uint32_t _m = (uint32_t)(mb), _p = (uint32_t)(par), _d; \
    asm volatile("{\n\t.reg .pred p;\n\t" \
        "mbarrier.try_wait.parity.acquire.cta.shared::cta.b64 p, [%1], %2;\n\t" \
        "selp.b32 %0, 1, 0, p;\n\t}" : "=r"(_d) : "r"(_m), "r"(_p) : "memory"); \
    if (!_d) { \
        asm volatile("{\n\t.reg .pred P1;\n\t" \
            "WL_%=:\n\t" \
            "mbarrier.try_wait.parity.acquire.cta.shared::cta.b64 P1, [%0], %1, 0x989680;\n\t" \
            "@P1 bra.uni WD_%=;\n\tbra.uni WL_%=;\n\tWD_%=:\n\t}" \
            :: "r"(_m), "r"(_p) : "memory"); \
    } } while (0)
#define CLUSTER_SYNC() do { \
    asm volatile("barrier.cluster.arrive.aligned;" ::: "memory"); \
    asm volatile("barrier.cluster.wait.aligned;"   ::: "memory"); } while (0)
#define STREAM_BAR(id) \
    asm volatile("bar.sync %0, 128;" :: "r"(id) : "memory")

// D += A(16x16) * B(16x8)^T, bf16 -> f32
__device__ __forceinline__ void mma16(float* d, uint32_t a0, uint32_t a1, uint32_t a2,
                                      uint32_t a3, uint32_t b0, uint32_t b1) {
    asm volatile(
        "mma.sync.aligned.m16n8k16.row.col.f32.bf16.bf16.f32 "
        "{%0,%1,%2,%3}, {%4,%5,%6,%7}, {%8,%9}, {%0,%1,%2,%3};"
        : "+f"(d[0]), "+f"(d[1]), "+f"(d[2]), "+f"(d[3])
        : "r"(a0), "r"(a1), "r"(a2), "r"(a3), "r"(b0), "r"(b1));
}

__global__ void __launch_bounds__(NTH, 1) __cluster_dims__(CLUSTER, 1, 1)
gru_wreg(const float* __restrict__ x,      // [B, T, I]
         const float* __restrict__ w_ih,   // [3H, I]
         const float* __restrict__ w_hh,   // [3H, H]
         const float* __restrict__ b_ih,   // [3H]
         const float* __restrict__ b_hh,   // [3H]
         const float* __restrict__ w_lin,  // [1, H]
         const float* __restrict__ b_lin,  // [1]
         float* __restrict__ out)          // [2B]
{
    extern __shared__ char smem[];
    __shared__ __align__(8) uint64_t mbars[4];   // [stream][parity]
    const uint32_t sbase = smem_u32(smem);

    const int tid  = threadIdx.x;
    const int wid  = tid >> 5;
    const int lane = tid & 31;
    const int gw   = wid >> 2;         // stream 0/1
    const int oct  = wid & 3;          // unit octet within stream
    const int g    = lane >> 2;        // fragment row 0..7
    const int c    = lane & 3;         // fragment k-lane 0..3
    const int gtid = tid & 127;        // thread id within stream
    const int rank = blockIdx.x;       // cluster rank: units rank*32..+32
    const int bg   = blockIdx.y;       // batch group (rows bg*32..+32)

    // ---- zero all 4 activation buffers (h(0)=0, pads clean) ----
    for (int e = tid; e < 4 * ABUF / 4; e += NTH)
        *(uint32_t*)(smem + WBYTES + e * 4) = 0u;

    // ---- weights -> SMEM bf16, permuted. rows: chain*32+u; chains r,z,nh,nx ----
    for (int e = tid; e < WROWS * PB; e += NTH) {
        int row = e / PB, k = e - row * PB;
        int ch = row >> 5, u = row & 31, gu = rank * 32 + u;
        float v = 0.f;
        if (k < 320) {
            if (ch == 0) {
                v = (k < HDIM) ? w_hh[(size_t)gu * HDIM + k]
                               : w_ih[(size_t)gu * IDIM + (k - HDIM)];
            } else if (ch == 1) {
                int gr = HDIM + gu;
                v = (k < HDIM) ? w_hh[(size_t)gr * HDIM + k]
                               : w_ih[(size_t)gr * IDIM + (k - HDIM)];
            } else if (ch == 2) {
                if (k < HDIM) v = w_hh[(size_t)(2 * HDIM + gu) * HDIM + k];
            } else {
                if (k >= HDIM) v = w_ih[(size_t)(2 * HDIM + gu) * IDIM + (k - HDIM)];
            }
        }
        *(__nv_bfloat16*)(smem + row * ROWB + (k < 320 ? perm(k) : k) * 2) =
            __float2bfloat16(v);
    }

    // ---- per-thread biases for my 2 units ----
    const int u0 = oct * 8 + 2 * c;
    float bR[2], bZ[2], bIN[2], bHN[2];
#pragma unroll
    for (int j = 0; j < 2; j++) {
        int gu = rank * 32 + u0 + j;
        bR[j]  = b_ih[gu] + b_hh[gu];
        bZ[j]  = b_ih[HDIM + gu] + b_hh[HDIM + gu];
        bIN[j] = b_ih[2 * HDIM + gu];
        bHN[j] = b_hh[2 * HDIM + gu];
    }

    // ---- stage x(0) into buffer [gw][0], slabs 16..19 ----
    const float* xgrp = x + (size_t)(bg * 32 + gw * MTG) * XSTR;
    {
        const uint32_t b0 = WBYTES + (uint32_t)(gw * 2) * ABUF;
#pragma unroll
        for (int q = 0; q < 2; q++) {
            int fi = gtid + q * 128;
            int row = fi >> 4, c4 = fi & 15;
            int kb = 16 + (c4 >> 2), m = c4 & 3;
            float4 v = __ldg((const float4*)(xgrp + (size_t)row * XSTR + c4 * 4));
            char* slab = smem + b0 + kb * SLAB + row * 32;
            *(uint32_t*)(slab + pos16(4 * m))     = pack_bf16x2(v.x, v.y);
            *(uint32_t*)(slab + pos16(4 * m + 2)) = pack_bf16x2(v.z, v.w);
        }
    }
    if (tid == 0) {
#pragma unroll
        for (int i = 0; i < 4; i++) MBARRIER_INIT(smem_u32(&mbars[i]), 128);
    }
    __syncthreads();

    // ---- hoist weight fragments into registers (step-invariant) ----
    const uint32_t bR_a = sbase + (uint32_t)(oct * 8 + g) * ROWB + 8u * c;
    const uint32_t bZ_a = bR_a + 32u * ROWB;
    const uint32_t bH_a = bR_a + 64u * ROWB;
    const uint32_t bX_a = bR_a + 96u * ROWB;
    uint32_t wR[20][2], wZ[20][2], wN[20][2];   // wN: nh for kb<16, nx for kb>=16
#pragma unroll
    for (int kb = 0; kb < 20; kb++) {
        const uint32_t o = (uint32_t)kb * 32u;
        lds2(wR[kb][0], wR[kb][1], bR_a + o);
        lds2(wZ[kb][0], wZ[kb][1], bZ_a + o);
        lds2(wN[kb][0], wN[kb][1], (kb < 16 ? bH_a : bX_a) + o);
    }

    CLUSTER_SYNC();   // mbarriers + buffers visible cluster-wide before any bulk copy

    // ---- per-warp A fragment addresses ----
    const uint32_t abuf_s = sbase + WBYTES;
    const uint32_t aoff = (uint32_t)g * 32 + 8u * c;           // + bi*ABUF + kb*SLAB
    float hprev[4] = {0.f, 0.f, 0.f, 0.f};
    int ph[2] = {0, 0};
    const uint32_t mb_s = smem_u32(&mbars[gw * 2]);
    const int peer = (gtid < 7) ? (gtid < rank ? gtid : gtid + 1) : 0;
    const uint32_t myslab_off = (uint32_t)(2 * rank) * SLAB;
    const uint32_t est = ((u0 >> 4) ? SLAB : 0) + (uint32_t)g * 32 + (uint32_t)pos16(u0 & 15);

#pragma unroll 1
    for (int t = 0; t < SEQT; ++t) {
        const uint32_t npar = (t + 1) & 1;
        const uint32_t nb_off = WBYTES + (uint32_t)(gw * 2 + npar) * ABUF;

        // ---- prefetch + store x(t+1) BEFORE the wait (x slabs are stream-local;
        //      prior-step reads by my stream are sequenced by last STREAM_BAR) ----
        if (t + 1 < SEQT) {
#pragma unroll
            for (int q = 0; q < 2; q++) {
                int fi = gtid + q * 128;
                int row = fi >> 4, c4 = fi & 15;
                int kb = 16 + (c4 >> 2), m = c4 & 3;
                float4 v = __ldg((const float4*)(xgrp + (size_t)row * XSTR
                                                 + (size_t)(t + 1) * IDIM + c4 * 4));
                char* slab = smem + nb_off + kb * SLAB + row * 32;
                *(uint32_t*)(slab + pos16(4 * m))     = pack_bf16x2(v.x, v.y);
                *(uint32_t*)(slab + pos16(4 * m + 2)) = pack_bf16x2(v.z, v.w);
            }
        }

        // ---- wait for h(t) ----
        if (t > 0) {
            int m = t & 1;
            MBARRIER_WAIT_PARITY(mb_s + 8u * m, ph[m]);
            ph[m] ^= 1;
        }

        // ---- HMMA over 20 k-slabs: A from SMEM, B from registers ----
        const uint32_t acur = abuf_s + (uint32_t)(gw * 2 + (t & 1)) * ABUF + aoff;
        float dR[4] = {0, 0, 0, 0}, dZ[4] = {0, 0, 0, 0};
        float dH[4] = {0, 0, 0, 0}, dX[4] = {0, 0, 0, 0};
#pragma unroll
        for (int kb = 0; kb < 20; kb++) {
            const uint32_t ao = acur + (uint32_t)kb * SLAB;
            uint32_t a0, a2, a1, a3;
            lds2(a0, a2, ao);
            lds2(a1, a3, ao + 256);
            mma16(dR, a0, a1, a2, a3, wR[kb][0], wR[kb][1]);
            mma16(dZ, a0, a1, a2, a3, wZ[kb][0], wZ[kb][1]);
            if (kb < 16) mma16(dH, a0, a1, a2, a3, wN[kb][0], wN[kb][1]);
            else         mma16(dX, a0, a1, a2, a3, wN[kb][0], wN[kb][1]);
        }

        // ---- gate epilogue (register-local; exact fp32 hprev) ----
        float hn[4];
#pragma unroll
        for (int i = 0; i < 4; i++) {
            int j = i & 1;
            float r = sigf(dR[i] + bR[j]);
            float z = sigf(dZ[i] + bZ[j]);
            float n = tanh_acc(dX[i] + bIN[j] + r * (dH[i] + bHN[j]));
            hn[i] = fmaf(z, hprev[i] - n, n);
            hprev[i] = hn[i];
        }

        // ---- local STS of my h slab block, stream barrier ----
        {
            char* dst = smem + nb_off + myslab_off + est;
            *(uint32_t*)(dst)       = pack_bf16x2(hn[0], hn[1]);   // row g
            *(uint32_t*)(dst + 256) = pack_bf16x2(hn[2], hn[3]);   // row g+8
        }
        STREAM_BAR(1 + gw);

        // ---- exchange: 7 bulk copies (1KB each) + arrivals ----
        const uint32_t lmb = mb_s + 8u * npar;
        if (gtid < 7) {
            asm volatile("fence.proxy.async.shared::cta;" ::: "memory");
            uint32_t src = sbase + nb_off + myslab_off;
            uint32_t dst = mapa_u32(src, peer);
            uint32_t rmb = mapa_u32(lmb, peer);
            bulk_to_peer(dst, src, 1024u, rmb);
        }
        if (gtid == 0) { MBARRIER_ARRIVE_EXPECT_TX(lmb, TXB); }
        else           { MBARRIER_ARRIVE(lmb); }
    }

    // ---- final wait: h(512) fully delivered into buffer [gw][0] ----
    MBARRIER_WAIT_PARITY(mb_s, ph[0]);

    // ---- head (rank 0): p = sigmoid(h_last . w_lin + b_lin); out = [p, 1-p] ----
    if (rank == 0) {
        const int row = gtid >> 3, seg = gtid & 7;
        const uint32_t hb = WBYTES + (uint32_t)(gw * 2) * ABUF;
        float s = 0.f;
#pragma unroll
        for (int kk = 0; kk < 32; kk++) {
            int k = seg * 32 + kk;
            const char* p8 = smem + hb + (k >> 4) * SLAB + row * 32 + pos16(k & 15);
            float hv = __bfloat162float(*(const __nv_bfloat16*)p8);
            s = fmaf(hv, __ldg(w_lin + k), s);
        }
        s += __shfl_xor_sync(0xffffffffu, s, 1);
        s += __shfl_xor_sync(0xffffffffu, s, 2);
        s += __shfl_xor_sync(0xffffffffu, s, 4);
        if (seg == 0) {
            float p = sigf(s + __ldg(b_lin));
            int gb = bg * 32 + gw * MTG + row;
            out[2 * gb]     = p;
            out[2 * gb + 1] = 1.f - p;
        }
    }

    CLUSTER_SYNC();   // no CTA exits while peers may still target its SMEM
}

extern "C" void kernel_launch(void* const* d_in, const int* in_sizes, int n_in,
                              void* d_out, int out_size) {
    const float* x     = (const float*)d_in[0];
    const float* w_ih0 = (const float*)d_in[1];
    const float* w_hh0 = (const float*)d_in[2];
    const float* b_ih0 = (const float*)d_in[3];
    const float* b_hh0 = (const float*)d_in[4];
    // d_in[5..8]: layer-1 GRU weights — dead code (output uses layer-0 h_last only)
    const float* w_lin = (const float*)d_in[9];
    const float* b_lin = (const float*)d_in[10];
    float* out = (float*)d_out;

    cudaFuncSetAttribute(gru_wreg, cudaFuncAttributeMaxDynamicSharedMemorySize, SMEMSZ);

    dim3 grid(CLUSTER, NBG);   // 8 x 16 = 128 CTAs = 16 clusters of 8
    gru_wreg<<<grid, NTH, SMEMSZ>>>(x, w_ih0, w_hh0, b_ih0, b_hh0, w_lin, b_lin, out);
}

// round 9
// speedup vs baseline: 4.2959x; 1.2147x over previous
#include <cuda_runtime.h>
#include <cuda_bf16.h>
#include <cstdint>

// ---------------- problem dims ----------------
#define SEQT  512
#define IDIM  64
#define HDIM  256
#define XSTR  ((size_t)SEQT * IDIM)

// ---------------- tiling ----------------
#define CLUSTER 8        // CTAs per cluster: each owns 32 hidden units
#define NBG     8        // batch groups (clusters); 64 rows each = 4 streams x 16
#define NSTR    4        // independent recurrence streams per CTA
#define MTG     16       // batch rows per stream
#define NTH     512      // 16 warps: 4 per stream
#define PB      336      // weight row pitch in bf16 (336 % 64 == 16 -> conflict-free)
#define ROWB    (PB * 2) // 672 bytes per weight row
#define WROWS   128      // gate rows per CTA: 4 chains (r,z,nh,nx) x 32 units
#define WBYTES  (WROWS * ROWB)          // 86016 (multiple of 512)
// A buffers: k-slab-major. 20 slabs x (16 rows x 16 cols bf16) = 20 x 512B
#define SLAB    512
#define ABUF    (20 * SLAB)             // 10240 per [stream][parity] buffer
#define SMEMSZ  (WBYTES + 2 * NSTR * ABUF)   // 167936
#define TXB     (7 * 1024)              // bulk-tx bytes expected per stream phase

// within-16-col fragment order: elem e -> byte offset in a 32B row
__device__ __forceinline__ int pos16(int e) {
    return ((e >> 1) & 3) * 8 + ((e >> 3) << 2) + (e & 1) * 2;
}
// weight-side perm across full k (same order per 16-block)
__device__ __forceinline__ int perm(int k) {
    int j = k & 15;
    return (k & ~15) + ((j >> 1) & 3) * 4 + ((j >> 3) << 1) + (j & 1);
}

__device__ __forceinline__ float sigf(float v) { return 1.0f / (1.0f + __expf(-v)); }
__device__ __forceinline__ float tanh_acc(float v) {
    v = fminf(fmaxf(v, -10.f), 10.f);
    float e = __expf(-2.f * v);
    return __fdividef(1.f - e, 1.f + e);
}

__device__ __forceinline__ uint32_t smem_u32(const void* p) {
    uint32_t a;
    asm("{ .reg .u64 t; cvta.to.shared.u64 t, %1; cvt.u32.u64 %0, t; }" : "=r"(a) : "l"(p));
    return a;
}
__device__ __forceinline__ uint32_t pack_bf16x2(float lo, float hi) {
    uint32_t r;
    asm("cvt.rn.bf16x2.f32 %0, %1, %2;" : "=r"(r) : "f"(hi), "f"(lo));
    return r;
}
__device__ __forceinline__ void lds2(uint32_t& x, uint32_t& y, uint32_t addr) {
    asm volatile("ld.shared.v2.b32 {%0, %1}, [%2];" : "=r"(x), "=r"(y) : "r"(addr));
}
__device__ __forceinline__ uint32_t mapa_u32(uint32_t laddr, int rank) {
    uint32_t r;
    asm("mapa.shared::cluster.u32 %0, %1, %2;" : "=r"(r) : "r"(laddr), "r"(rank));
    return r;
}
__device__ __forceinline__ void bulk_to_peer(uint32_t dst_cluster, uint32_t src_cta,
                                             uint32_t bytes, uint32_t rmbar) {
    asm volatile("cp.async.bulk.shared::cluster.shared::cta.mbarrier::complete_tx::bytes "
                 "[%0], [%1], %2, [%3];"
                 :: "r"(dst_cluster), "r"(src_cta), "r"(bytes), "r"(rmbar) : "memory");
}
#define MBARRIER_INIT(mb, c) \
    asm volatile("mbarrier.init.shared.b64 [%0], %1;" \
                 :: "r"((uint32_t)(mb)), "r"((uint32_t)(c)) : "memory")
#define MBARRIER_ARRIVE(mb) \
    asm volatile("mbarrier.arrive.shared.b64 _, [%0];" :: "r"((uint32_t)(mb)) : "memory")
#define MBARRIER_ARRIVE_EXPECT_TX(mb, n) \
    asm volatile("mbarrier.arrive.expect_tx.shared.b64 _, [%0], %1;" \
                 :: "r"((uint32_t)(mb)), "r"((uint32_t)(n)) : "memory")
#define MBARRIER_WAIT_PARITY(mb, par) do { \
    uint32_t _m = (uint32_t)(mb), _p = (uint32_t)(par), _d; \
    asm volatile("{\n\t.reg .pred p;\n\t" \
        "mbarrier.try_wait.parity.acquire.cta.shared::cta.b64 p, [%1], %2;\n\t" \
        "selp.b32 %0, 1, 0, p;\n\t}" : "=r"(_d) : "r"(_m), "r"(_p) : "memory"); \
    if (!_d) { \
        asm volatile("{\n\t.reg .pred P1;\n\t" \
            "WL_%=:\n\t" \
            "mbarrier.try_wait.parity.acquire.cta.shared::cta.b64 P1, [%0], %1, 0x989680;\n\t" \
            "@P1 bra.uni WD_%=;\n\tbra.uni WL_%=;\n\tWD_%=:\n\t}" \
            :: "r"(_m), "r"(_p) : "memory"); \
    } } while (0)
#define CLUSTER_SYNC() do { \
    asm volatile("barrier.cluster.arrive.aligned;" ::: "memory"); \
    asm volatile("barrier.cluster.wait.aligned;"   ::: "memory"); } while (0)
#define STREAM_BAR(id) \
    asm volatile("bar.sync %0, 128;" :: "r"(id) : "memory")

// D += A(16x16) * B(16x8)^T, bf16 -> f32
__device__ __forceinline__ void mma16(float* d, uint32_t a0, uint32_t a1, uint32_t a2,
                                      uint32_t a3, uint32_t b0, uint32_t b1) {
    asm volatile(
        "mma.sync.aligned.m16n8k16.row.col.f32.bf16.bf16.f32 "
        "{%0,%1,%2,%3}, {%4,%5,%6,%7}, {%8,%9}, {%0,%1,%2,%3};"
        : "+f"(d[0]), "+f"(d[1]), "+f"(d[2]), "+f"(d[3])
        : "r"(a0), "r"(a1), "r"(a2), "r"(a3), "r"(b0), "r"(b1));
}

__global__ void __launch_bounds__(NTH, 1) __cluster_dims__(CLUSTER, 1, 1)
gru_s4(const float* __restrict__ x,      // [B, T, I]
       const float* __restrict__ w_ih,   // [3H, I]
       const float* __restrict__ w_hh,   // [3H, H]
       const float* __restrict__ b_ih,   // [3H]
       const float* __restrict__ b_hh,   // [3H]
       const float* __restrict__ w_lin,  // [1, H]
       const float* __restrict__ b_lin,  // [1]
       float* __restrict__ out)          // [2B]
{
    extern __shared__ char smem[];
    __shared__ __align__(8) uint64_t mbars[2 * NSTR];   // [stream][parity]
    const uint32_t sbase = smem_u32(smem);

    const int tid  = threadIdx.x;
    const int wid  = tid >> 5;
    const int lane = tid & 31;
    const int gw   = wid >> 2;         // stream 0..3
    const int oct  = wid & 3;          // unit octet within stream
    const int g    = lane >> 2;        // fragment row 0..7
    const int c    = lane & 3;         // fragment k-lane 0..3
    const int gtid = tid & 127;        // thread id within stream
    const int rank = blockIdx.x;       // cluster rank: units rank*32..+32
    const int bg   = blockIdx.y;       // batch group (rows bg*64..+64)

    // ---- zero all activation buffers (h(0)=0, pads clean) ----
    for (int e = tid; e < 2 * NSTR * ABUF / 4; e += NTH)
        *(uint32_t*)(smem + WBYTES + e * 4) = 0u;

    // ---- weights -> SMEM bf16, permuted. rows: chain*32+u; chains r,z,nh,nx ----
    for (int e = tid; e < WROWS * PB; e += NTH) {
        int row = e / PB, k = e - row * PB;
        int ch = row >> 5, u = row & 31, gu = rank * 32 + u;
        float v = 0.f;
        if (k < 320) {
            if (ch == 0) {
                v = (k < HDIM) ? w_hh[(size_t)gu * HDIM + k]
                               : w_ih[(size_t)gu * IDIM + (k - HDIM)];
            } else if (ch == 1) {
                int gr = HDIM + gu;
                v = (k < HDIM) ? w_hh[(size_t)gr * HDIM + k]
                               : w_ih[(size_t)gr * IDIM + (k - HDIM)];
            } else if (ch == 2) {
                if (k < HDIM) v = w_hh[(size_t)(2 * HDIM + gu) * HDIM + k];
            } else {
                if (k >= HDIM) v = w_ih[(size_t)(2 * HDIM + gu) * IDIM + (k - HDIM)];
            }
        }
        *(__nv_bfloat16*)(smem + row * ROWB + (k < 320 ? perm(k) : k) * 2) =
            __float2bfloat16(v);
    }

    // ---- per-thread biases for my 2 units ----
    const int u0 = oct * 8 + 2 * c;
    float bR[2], bZ[2], bIN[2], bHN[2];
#pragma unroll
    for (int j = 0; j < 2; j++) {
        int gu = rank * 32 + u0 + j;
        bR[j]  = b_ih[gu] + b_hh[gu];
        bZ[j]  = b_ih[HDIM + gu] + b_hh[HDIM + gu];
        bIN[j] = b_ih[2 * HDIM + gu];
        bHN[j] = b_hh[2 * HDIM + gu];
    }

    // ---- stage x(0) into buffer [gw][0], slabs 16..19 ----
    const float* xgrp = x + (size_t)(bg * (NSTR * MTG) + gw * MTG) * XSTR;
    {
        const uint32_t b0 = WBYTES + (uint32_t)(gw * 2) * ABUF;
#pragma unroll
        for (int q = 0; q < 2; q++) {
            int fi = gtid + q * 128;
            int row = fi >> 4, c4 = fi & 15;
            int kb = 16 + (c4 >> 2), m = c4 & 3;
            float4 v = __ldg((const float4*)(xgrp + (size_t)row * XSTR + c4 * 4));
            char* slab = smem + b0 + kb * SLAB + row * 32;
            *(uint32_t*)(slab + pos16(4 * m))     = pack_bf16x2(v.x, v.y);
            *(uint32_t*)(slab + pos16(4 * m + 2)) = pack_bf16x2(v.z, v.w);
        }
    }
    if (tid == 0) {
#pragma unroll
        for (int i = 0; i < 2 * NSTR; i++) MBARRIER_INIT(smem_u32(&mbars[i]), 128);
    }
    __syncthreads();
    CLUSTER_SYNC();   // mbarriers + buffers visible cluster-wide before any bulk copy

    // ---- per-warp addresses ----
    const uint32_t abuf_s = sbase + WBYTES;
    const uint32_t aoff = (uint32_t)g * 32 + 8u * c;           // + bi*ABUF + kb*SLAB
    const uint32_t bR_a = sbase + (uint32_t)(oct * 8 + g) * ROWB + 8u * c;
    const uint32_t bZ_a = bR_a + 32u * ROWB;
    const uint32_t bH_a = bR_a + 64u * ROWB;
    const uint32_t bX_a = bR_a + 96u * ROWB;

    float hprev[4] = {0.f, 0.f, 0.f, 0.f};
    int ph[2] = {0, 0};
    const uint32_t mb_s = smem_u32(&mbars[gw * 2]);      // my stream's 2 mbars
    const int peer = (gtid < 7) ? (gtid < rank ? gtid : gtid + 1) : 0;
    const uint32_t myslab_off = (uint32_t)(2 * rank) * SLAB;
    const uint32_t est = ((u0 >> 4) ? SLAB : 0) + (uint32_t)g * 32 + (uint32_t)pos16(u0 & 15);

#pragma unroll 1
    for (int t = 0; t < SEQT; ++t) {
        const uint32_t npar = (t + 1) & 1;
        const uint32_t nb_off = WBYTES + (uint32_t)(gw * 2 + npar) * ABUF;

        // ---- prefetch + store x(t+1) BEFORE the wait (x slabs are stream-local;
        //      prior-step reads by my stream are sequenced by last STREAM_BAR) ----
        if (t + 1 < SEQT) {
#pragma unroll
            for (int q = 0; q < 2; q++) {
                int fi = gtid + q * 128;
                int row = fi >> 4, c4 = fi & 15;
                int kb = 16 + (c4 >> 2), m = c4 & 3;
                float4 v = __ldg((const float4*)(xgrp + (size_t)row * XSTR
                                                 + (size_t)(t + 1) * IDIM + c4 * 4));
                char* slab = smem + nb_off + kb * SLAB + row * 32;
                *(uint32_t*)(slab + pos16(4 * m))     = pack_bf16x2(v.x, v.y);
                *(uint32_t*)(slab + pos16(4 * m + 2)) = pack_bf16x2(v.z, v.w);
            }
        }

        // ---- wait for h(t) ----
        if (t > 0) {
            int m = t & 1;
            MBARRIER_WAIT_PARITY(mb_s + 8u * m, ph[m]);
            ph[m] ^= 1;
        }

        // ---- HMMA over 20 k-slabs: A and B from SMEM ----
        const uint32_t acur = abuf_s + (uint32_t)(gw * 2 + (t & 1)) * ABUF + aoff;
        float dR[4] = {0, 0, 0, 0}, dZ[4] = {0, 0, 0, 0};
        float dH[4] = {0, 0, 0, 0}, dX[4] = {0, 0, 0, 0};
#pragma unroll
        for (int kb = 0; kb < 20; kb++) {
            const uint32_t ao = acur + (uint32_t)kb * SLAB;
            const uint32_t wo = (uint32_t)kb * 32u;
            uint32_t a0, a2, a1, a3, r0, r1, z0, z1, n0, n1;
            lds2(a0, a2, ao);
            lds2(a1, a3, ao + 256);
            lds2(r0, r1, bR_a + wo);
            lds2(z0, z1, bZ_a + wo);
            if (kb < 16) { lds2(n0, n1, bH_a + wo); }
            else         { lds2(n0, n1, bX_a + wo); }
            mma16(dR, a0, a1, a2, a3, r0, r1);
            mma16(dZ, a0, a1, a2, a3, z0, z1);
            if (kb < 16) mma16(dH, a0, a1, a2, a3, n0, n1);
            else         mma16(dX, a0, a1, a2, a3, n0, n1);
        }

        // ---- gate epilogue (register-local; exact fp32 hprev) ----
        float hn[4];
#pragma unroll
        for (int i = 0; i < 4; i++) {
            int j = i & 1;
            float r = sigf(dR[i] + bR[j]);
            float z = sigf(dZ[i] + bZ[j]);
            float n = tanh_acc(dX[i] + bIN[j] + r * (dH[i] + bHN[j]));
            hn[i] = fmaf(z, hprev[i] - n, n);
            hprev[i] = hn[i];
        }

        // ---- local STS of my h slab block, stream barrier ----
        {
            char* dst = smem + nb_off + myslab_off + est;
            *(uint32_t*)(dst)       = pack_bf16x2(hn[0], hn[1]);   // row g
            *(uint32_t*)(dst + 256) = pack_bf16x2(hn[2], hn[3]);   // row g+8
        }
        STREAM_BAR(1 + gw);

        // ---- exchange: 7 bulk copies (1KB each) + arrivals ----
        const uint32_t lmb = mb_s + 8u * npar;
        if (gtid < 7) {
            asm volatile("fence.proxy.async.shared::cta;" ::: "memory");
            uint32_t src = sbase + nb_off + myslab_off;
            uint32_t dst = mapa_u32(src, peer);
            uint32_t rmb = mapa_u32(lmb, peer);
            bulk_to_peer(dst, src, 1024u, rmb);
        }
        if (gtid == 0) { MBARRIER_ARRIVE_EXPECT_TX(lmb, TXB); }
        else           { MBARRIER_ARRIVE(lmb); }
    }

    // ---- final wait: h(512) fully delivered into buffer [gw][0] ----
    MBARRIER_WAIT_PARITY(mb_s, ph[0]);

    // ---- head (rank 0): p = sigmoid(h_last . w_lin + b_lin); out = [p, 1-p] ----
    if (rank == 0) {
        const int row = gtid >> 3, seg = gtid & 7;
        const uint32_t hb = WBYTES + (uint32_t)(gw * 2) * ABUF;
        float s = 0.f;
#pragma unroll
        for (int kk = 0; kk < 32; kk++) {
            int k = seg * 32 + kk;
            const char* p8 = smem + hb + (k >> 4) * SLAB + row * 32 + pos16(k & 15);
            float hv = __bfloat162float(*(const __nv_bfloat16*)p8);
            s = fmaf(hv, __ldg(w_lin + k), s);
        }
        s += __shfl_xor_sync(0xffffffffu, s, 1);
        s += __shfl_xor_sync(0xffffffffu, s, 2);
        s += __shfl_xor_sync(0xffffffffu, s, 4);
        if (seg == 0) {
            float p = sigf(s + __ldg(b_lin));
            int gb = bg * (NSTR * MTG) + gw * MTG + row;
            out[2 * gb]     = p;
            out[2 * gb + 1] = 1.f - p;
        }
    }

    CLUSTER_SYNC();   // no CTA exits while peers may still target its SMEM
}

extern "C" void kernel_launch(void* const* d_in, const int* in_sizes, int n_in,
                              void* d_out, int out_size) {
    const float* x     = (const float*)d_in[0];
    const float* w_ih0 = (const float*)d_in[1];
    const float* w_hh0 = (const float*)d_in[2];
    const float* b_ih0 = (const float*)d_in[3];
    const float* b_hh0 = (const float*)d_in[4];
    // d_in[5..8]: layer-1 GRU weights — dead code (output uses layer-0 h_last only)
    const float* w_lin = (const float*)d_in[9];
    const float* b_lin = (const float*)d_in[10];
    float* out = (float*)d_out;

    cudaFuncSetAttribute(gru_s4, cudaFuncAttributeMaxDynamicSharedMemorySize, SMEMSZ);

    dim3 grid(CLUSTER, NBG);   // 8 x 8 = 64 CTAs = 8 clusters of 8, 4 streams each
    gru_s4<<<grid, NTH, SMEMSZ>>>(x, w_ih0, w_hh0, b_ih0, b_hh0, w_lin, b_lin, out);
}

// round 10
// speedup vs baseline: 4.7931x; 1.1157x over previous
#include <cuda_runtime.h>
#include <cuda_bf16.h>
#include <cstdint>

// ---------------- problem dims ----------------
#define SEQT  512
#define IDIM  64
#define HDIM  256
#define XSTR  ((size_t)SEQT * IDIM)

// ---------------- tiling ----------------
#define CLUSTER 8        // CTAs per cluster: each owns 32 hidden units
#define NBG     8        // batch groups (clusters); 64 rows each = 4 streams x 16
#define NSTR    4        // independent recurrence streams per CTA
#define MTG     16       // batch rows per stream
#define NTH     512      // 16 warps: 4 per stream
#define PB      336      // weight row pitch in bf16 (336 % 64 == 16 -> conflict-free)
#define ROWB    (PB * 2) // 672 bytes per weight row
#define WROWS   128      // gate rows per CTA: 4 chains (r,z,nh,nx) x 32 units
#define WBYTES  (WROWS * ROWB)          // 86016 (multiple of 512)
#define SLAB    512
#define ABUF    (20 * SLAB)             // 10240 per [stream][parity] buffer
#define SMEMSZ  (WBYTES + 2 * NSTR * ABUF)   // 167936
#define TXB     (7 * 1024)              // bulk-tx bytes expected per stream phase

// within-16-col fragment order: elem e -> byte offset in a 32B row
__device__ __forceinline__ int pos16(int e) {
    return ((e >> 1) & 3) * 8 + ((e >> 3) << 2) + (e & 1) * 2;
}
// weight-side perm across full k (same order per 16-block)
__device__ __forceinline__ int perm(int k) {
    int j = k & 15;
    return (k & ~15) + ((j >> 1) & 3) * 4 + ((j >> 3) << 1) + (j & 1);
}

__device__ __forceinline__ float sigf(float v) { return 1.0f / (1.0f + __expf(-v)); }
__device__ __forceinline__ float tanh_acc(float v) {
    v = fminf(fmaxf(v, -10.f), 10.f);
    float e = __expf(-2.f * v);
    return __fdividef(1.f - e, 1.f + e);
}

__device__ __forceinline__ uint32_t smem_u32(const void* p) {
    uint32_t a;
    asm("{ .reg .u64 t; cvta.to.shared.u64 t, %1; cvt.u32.u64 %0, t; }" : "=r"(a) : "l"(p));
    return a;
}
__device__ __forceinline__ uint32_t pack_bf16x2(float lo, float hi) {
    uint32_t r;
    asm("cvt.rn.bf16x2.f32 %0, %1, %2;" : "=r"(r) : "f"(hi), "f"(lo));
    return r;
}
__device__ __forceinline__ void lds2(uint32_t& x, uint32_t& y, uint32_t addr) {
    asm volatile("ld.shared.v2.b32 {%0, %1}, [%2];" : "=r"(x), "=r"(y) : "r"(addr));
}
__device__ __forceinline__ uint32_t mapa_u32(uint32_t laddr, int rank) {
    uint32_t r;
    asm("mapa.shared::cluster.u32 %0, %1, %2;" : "=r"(r) : "r"(laddr), "r"(rank));
    return r;
}
__device__ __forceinline__ void bulk_to_peer(uint32_t dst_cluster, uint32_t src_cta,
                                             uint32_t bytes, uint32_t rmbar) {
    asm volatile("cp.async.bulk.shared::cluster.shared::cta.mbarrier::complete_tx::bytes "
                 "[%0], [%1], %2, [%3];"
                 :: "r"(dst_cluster), "r"(src_cta), "r"(bytes), "r"(rmbar) : "memory");
}
#define MBARRIER_INIT(mb, c) \
    asm volatile("mbarrier.init.shared.b64 [%0], %1;" \
                 :: "r"((uint32_t)(mb)), "r"((uint32_t)(c)) : "memory")
#define MBARRIER_ARRIVE(mb) \
    asm volatile("mbarrier.arrive.shared.b64 _, [%0];" :: "r"((uint32_t)(mb)) : "memory")
#define MBARRIER_ARRIVE_EXPECT_TX(mb, n) \
    asm volatile("mbarrier.arrive.expect_tx.shared.b64 _, [%0], %1;" \
                 :: "r"((uint32_t)(mb)), "r"((uint32_t)(n)) : "memory")
#define MBARRIER_WAIT_PARITY(mb, par) do { \
    uint32_t _m = (uint32_t)(mb), _p = (uint32_t)(par), _d; \
    asm volatile("{\n\t.reg .pred p;\n\t" \
        "mbarrier.try_wait.parity.acquire.cta.shared::cta.b64 p, [%1], %2;\n\t" \
        "selp.b32 %0, 1, 0, p;\n\t}" : "=r"(_d) : "r"(_m), "r"(_p) : "memory"); \
    if (!_d) { \
        asm volatile("{\n\t.reg .pred P1;\n\t" \
            "WL_%=:\n\t" \
            "mbarrier.try_wait.parity.acquire.cta.shared::cta.b64 P1, [%0], %1, 0x989680;\n\t" \
            "@P1 bra.uni WD_%=;\n\tbra.uni WL_%=;\n\tWD_%=:\n\t}" \
            :: "r"(_m), "r"(_p) : "memory"); \
    } } while (0)
#define CLUSTER_SYNC() do { \
    asm volatile("barrier.cluster.arrive.aligned;" ::: "memory"); \
    asm volatile("barrier.cluster.wait.aligned;"   ::: "memory"); } while (0)
#define STREAM_BAR(id) \
    asm volatile("bar.sync %0, 128;" :: "r"(id) : "memory")

// D += A(16x16) * B(16x8)^T, bf16 -> f32
__device__ __forceinline__ void mma16(float* d, uint32_t a0, uint32_t a1, uint32_t a2,
                                      uint32_t a3, uint32_t b0, uint32_t b1) {
    asm volatile(
        "mma.sync.aligned.m16n8k16.row.col.f32.bf16.bf16.f32 "
        "{%0,%1,%2,%3}, {%4,%5,%6,%7}, {%8,%9}, {%0,%1,%2,%3};"
        : "+f"(d[0]), "+f"(d[1]), "+f"(d[2]), "+f"(d[3])
        : "r"(a0), "r"(a1), "r"(a2), "r"(a3), "r"(b0), "r"(b1));
}

__global__ void __launch_bounds__(NTH, 1) __cluster_dims__(CLUSTER, 1, 1)
gru_xpre(const float* __restrict__ x,      // [B, T, I]
         const float* __restrict__ w_ih,   // [3H, I]
         const float* __restrict__ w_hh,   // [3H, H]
         const float* __restrict__ b_ih,   // [3H]
         const float* __restrict__ b_hh,   // [3H]
         const float* __restrict__ w_lin,  // [1, H]
         const float* __restrict__ b_lin,  // [1]
         float* __restrict__ out)          // [2B]
{
    extern __shared__ char smem[];
    __shared__ __align__(8) uint64_t mbars[2 * NSTR];   // [stream][parity]
    const uint32_t sbase = smem_u32(smem);

    const int tid  = threadIdx.x;
    const int wid  = tid >> 5;
    const int lane = tid & 31;
    const int gw   = wid >> 2;         // stream 0..3
    const int oct  = wid & 3;          // unit octet within stream
    const int g    = lane >> 2;        // fragment row 0..7
    const int c    = lane & 3;         // fragment k-lane 0..3
    const int gtid = tid & 127;        // thread id within stream
    const int rank = blockIdx.x;       // cluster rank: units rank*32..+32
    const int bg   = blockIdx.y;       // batch group (rows bg*64..+64)

    // ---- zero all activation buffers (h(0)=0, pads clean) ----
    for (int e = tid; e < 2 * NSTR * ABUF / 4; e += NTH)
        *(uint32_t*)(smem + WBYTES + e * 4) = 0u;

    // ---- weights -> SMEM bf16, permuted. rows: chain*32+u; chains r,z,nh,nx ----
    for (int e = tid; e < WROWS * PB; e += NTH) {
        int row = e / PB, k = e - row * PB;
        int ch = row >> 5, u = row & 31, gu = rank * 32 + u;
        float v = 0.f;
        if (k < 320) {
            if (ch == 0) {
                v = (k < HDIM) ? w_hh[(size_t)gu * HDIM + k]
                               : w_ih[(size_t)gu * IDIM + (k - HDIM)];
            } else if (ch == 1) {
                int gr = HDIM + gu;
                v = (k < HDIM) ? w_hh[(size_t)gr * HDIM + k]
                               : w_ih[(size_t)gr * IDIM + (k - HDIM)];
            } else if (ch == 2) {
                if (k < HDIM) v = w_hh[(size_t)(2 * HDIM + gu) * HDIM + k];
            } else {
                if (k >= HDIM) v = w_ih[(size_t)(2 * HDIM + gu) * IDIM + (k - HDIM)];
            }
        }
        *(__nv_bfloat16*)(smem + row * ROWB + (k < 320 ? perm(k) : k) * 2) =
            __float2bfloat16(v);
    }

    // ---- per-thread biases for my 2 units ----
    const int u0 = oct * 8 + 2 * c;
    float bR[2], bZ[2], bIN[2], bHN[2];
#pragma unroll
    for (int j = 0; j < 2; j++) {
        int gu = rank * 32 + u0 + j;
        bR[j]  = b_ih[gu] + b_hh[gu];
        bZ[j]  = b_ih[HDIM + gu] + b_hh[HDIM + gu];
        bIN[j] = b_ih[2 * HDIM + gu];
        bHN[j] = b_hh[2 * HDIM + gu];
    }

    // ---- stage x(0) into buffer [gw][0], slabs 16..19 ----
    const float* xgrp = x + (size_t)(bg * (NSTR * MTG) + gw * MTG) * XSTR;
    {
        const uint32_t b0 = WBYTES + (uint32_t)(gw * 2) * ABUF;
#pragma unroll
        for (int q = 0; q < 2; q++) {
            int fi = gtid + q * 128;
            int row = fi >> 4, c4 = fi & 15;
            int kb = 16 + (c4 >> 2), m = c4 & 3;
            float4 v = __ldg((const float4*)(xgrp + (size_t)row * XSTR + c4 * 4));
            char* slab = smem + b0 + kb * SLAB + row * 32;
            *(uint32_t*)(slab + pos16(4 * m))     = pack_bf16x2(v.x, v.y);
            *(uint32_t*)(slab + pos16(4 * m + 2)) = pack_bf16x2(v.z, v.w);
        }
    }
    if (tid == 0) {
#pragma unroll
        for (int i = 0; i < 2 * NSTR; i++) MBARRIER_INIT(smem_u32(&mbars[i]), 128);
    }
    __syncthreads();

    // ---- per-warp addresses ----
    const uint32_t abuf_s = sbase + WBYTES;
    const uint32_t aoff = (uint32_t)g * 32 + 8u * c;           // + bi*ABUF + kb*SLAB
    const uint32_t bR_a = sbase + (uint32_t)(oct * 8 + g) * ROWB + 8u * c;
    const uint32_t bZ_a = bR_a + 32u * ROWB;
    const uint32_t bH_a = bR_a + 64u * ROWB;
    const uint32_t bX_a = bR_a + 96u * ROWB;

    // ---- hoist n-chain weight fragments into registers (step-invariant) ----
    uint32_t wNH[16][2], wNX[4][2];
#pragma unroll
    for (int kb = 0; kb < 16; kb++) lds2(wNH[kb][0], wNH[kb][1], bH_a + kb * 32u);
#pragma unroll
    for (int kb = 0; kb < 4; kb++)  lds2(wNX[kb][0], wNX[kb][1], bX_a + (16 + kb) * 32u);

    CLUSTER_SYNC();   // mbarriers + buffers visible cluster-wide before any bulk copy

    float hprev[4] = {0.f, 0.f, 0.f, 0.f};
    int ph[2] = {0, 0};
    const uint32_t mb_s = smem_u32(&mbars[gw * 2]);      // my stream's 2 mbars
    const int peer = (gtid < 7) ? (gtid < rank ? gtid : gtid + 1) : 0;
    const uint32_t myslab_off = (uint32_t)(2 * rank) * SLAB;
    const uint32_t est = ((u0 >> 4) ? SLAB : 0) + (uint32_t)g * 32 + (uint32_t)pos16(u0 & 15);

#pragma unroll 1
    for (int t = 0; t < SEQT; ++t) {
        const uint32_t npar = (t + 1) & 1;
        const uint32_t nb_off = WBYTES + (uint32_t)(gw * 2 + npar) * ABUF;
        const uint32_t acur = abuf_s + (uint32_t)(gw * 2 + (t & 1)) * ABUF + aoff;

        // ---- stage x(t+1) (pre-wait; stream-local slabs, sequenced by last bar) ----
        if (t + 1 < SEQT) {
#pragma unroll
            for (int q = 0; q < 2; q++) {
                int fi = gtid + q * 128;
                int row = fi >> 4, c4 = fi & 15;
                int kb = 16 + (c4 >> 2), m = c4 & 3;
                float4 v = __ldg((const float4*)(xgrp + (size_t)row * XSTR
                                                 + (size_t)(t + 1) * IDIM + c4 * 4));
                char* slab = smem + nb_off + kb * SLAB + row * 32;
                *(uint32_t*)(slab + pos16(4 * m))     = pack_bf16x2(v.x, v.y);
                *(uint32_t*)(slab + pos16(4 * m + 2)) = pack_bf16x2(v.z, v.w);
            }
        }

        // ---- pre-wait x-part MMA (kb 16..19): x(t) known since last iteration;
        //      disjoint from h slabs that in-flight bulk copies write ----
        float dR[4] = {0, 0, 0, 0}, dZ[4] = {0, 0, 0, 0};
        float dH[4] = {0, 0, 0, 0}, dX[4] = {0, 0, 0, 0};
#pragma unroll
        for (int kb = 16; kb < 20; kb++) {
            const uint32_t ao = acur + (uint32_t)kb * SLAB;
            const uint32_t wo = (uint32_t)kb * 32u;
            uint32_t a0, a2, a1, a3, r0, r1, z0, z1;
            lds2(a0, a2, ao);
            lds2(a1, a3, ao + 256);
            lds2(r0, r1, bR_a + wo);
            lds2(z0, z1, bZ_a + wo);
            mma16(dR, a0, a1, a2, a3, r0, r1);
            mma16(dZ, a0, a1, a2, a3, z0, z1);
            mma16(dX, a0, a1, a2, a3, wNX[kb - 16][0], wNX[kb - 16][1]);
        }

        // ---- wait for h(t) ----
        if (t > 0) {
            int m = t & 1;
            MBARRIER_WAIT_PARITY(mb_s + 8u * m, ph[m]);
            ph[m] ^= 1;

            // ---- post-wait h-part MMA (kb 0..15) ----
#pragma unroll
            for (int kb = 0; kb < 16; kb++) {
                const uint32_t ao = acur + (uint32_t)kb * SLAB;
                const uint32_t wo = (uint32_t)kb * 32u;
                uint32_t a0, a2, a1, a3, r0, r1, z0, z1;
                lds2(a0, a2, ao);
                lds2(a1, a3, ao + 256);
                lds2(r0, r1, bR_a + wo);
                lds2(z0, z1, bZ_a + wo);
                mma16(dR, a0, a1, a2, a3, r0, r1);
                mma16(dZ, a0, a1, a2, a3, z0, z1);
                mma16(dH, a0, a1, a2, a3, wNH[kb][0], wNH[kb][1]);
            }
        }

        // ---- gate epilogue (register-local; exact fp32 hprev) ----
        float hn[4];
#pragma unroll
        for (int i = 0; i < 4; i++) {
            int j = i & 1;
            float r = sigf(dR[i] + bR[j]);
            float z = sigf(dZ[i] + bZ[j]);
            float n = tanh_acc(dX[i] + bIN[j] + r * (dH[i] + bHN[j]));
            hn[i] = fmaf(z, hprev[i] - n, n);
            hprev[i] = hn[i];
        }

        // ---- local STS of my h slab block, stream barrier ----
        {
            char* dst = smem + nb_off + myslab_off + est;
            *(uint32_t*)(dst)       = pack_bf16x2(hn[0], hn[1]);   // row g
            *(uint32_t*)(dst + 256) = pack_bf16x2(hn[2], hn[3]);   // row g+8
        }
        STREAM_BAR(1 + gw);

        // ---- exchange: 7 bulk copies (1KB each) + arrivals ----
        const uint32_t lmb = mb_s + 8u * npar;
        if (gtid < 7) {
            asm volatile("fence.proxy.async.shared::cta;" ::: "memory");
            uint32_t src = sbase + nb_off + myslab_off;
            uint32_t dst = mapa_u32(src, peer);
            uint32_t rmb = mapa_u32(lmb, peer);
            bulk_to_peer(dst, src, 1024u, rmb);
        }
        if (gtid == 0) { MBARRIER_ARRIVE_EXPECT_TX(lmb, TXB); }
        else           { MBARRIER_ARRIVE(lmb); }
    }

    // ---- final wait: h(512) fully delivered into buffer [gw][0] ----
    MBARRIER_WAIT_PARITY(mb_s, ph[0]);

    // ---- head (rank 0): p = sigmoid(h_last . w_lin + b_lin); out = [p, 1-p] ----
    if (rank == 0) {
        const int row = gtid >> 3, seg = gtid & 7;
        const uint32_t hb = WBYTES + (uint32_t)(gw * 2) * ABUF;
        float s = 0.f;
#pragma unroll
        for (int kk = 0; kk < 32; kk++) {
            int k = seg * 32 + kk;
            const char* p8 = smem + hb + (k >> 4) * SLAB + row * 32 + pos16(k & 15);
            float hv = __bfloat162float(*(const __nv_bfloat16*)p8);
            s = fmaf(hv, __ldg(w_lin + k), s);
        }
        s += __shfl_xor_sync(0xffffffffu, s, 1);
        s += __shfl_xor_sync(0xffffffffu, s, 2);
        s += __shfl_xor_sync(0xffffffffu, s, 4);
        if (seg == 0) {
            float p = sigf(s + __ldg(b_lin));
            int gb = bg * (NSTR * MTG) + gw * MTG + row;
            out[2 * gb]     = p;
            out[2 * gb + 1] = 1.f - p;
        }
    }

    CLUSTER_SYNC();   // no CTA exits while peers may still target its SMEM
}

extern "C" void kernel_launch(void* const* d_in, const int* in_sizes, int n_in,
                              void* d_out, int out_size) {
    const float* x     = (const float*)d_in[0];
    const float* w_ih0 = (const float*)d_in[1];
    const float* w_hh0 = (const float*)d_in[2];
    const float* b_ih0 = (const float*)d_in[3];
    const float* b_hh0 = (const float*)d_in[4];
    // d_in[5..8]: layer-1 GRU weights — dead code (output uses layer-0 h_last only)
    const float* w_lin = (const float*)d_in[9];
    const float* b_lin = (const float*)d_in[10];
    float* out = (float*)d_out;

    cudaFuncSetAttribute(gru_xpre, cudaFuncAttributeMaxDynamicSharedMemorySize, SMEMSZ);

    dim3 grid(CLUSTER, NBG);   // 8 x 8 = 64 CTAs = 8 clusters of 8, 4 streams each
    gru_xpre<<<grid, NTH, SMEMSZ>>>(x, w_ih0, w_hh0, b_ih0, b_hh0, w_lin, b_lin, out);
}